// round 1
// baseline (speedup 1.0000x reference)
#include <cuda_runtime.h>

#define LOG2E 1.4426950408889634f

// ---- scratch (static __device__; no allocations allowed) ----
__device__ float g_h1[512*64*128];      // conv1 output   [b][c=64][t=128]
__device__ float g_feats[64*512*128];   // conv2 output   [t'=64][b][in=128]
__device__ float g_wns[64*512*128];     // sensory num    [t'][b][u]
__device__ float g_wds[64*512*128];     // sensory den    [t'][b][u]
__device__ float g_hT[512*128];         // final LTC state

__device__ __forceinline__ float fast_ex2(float x){ float y; asm("ex2.approx.f32 %0, %1;" : "=f"(y) : "f"(x)); return y; }
__device__ __forceinline__ float fast_rcp(float x){ float y; asm("rcp.approx.f32 %0, %1;" : "=f"(y) : "f"(x)); return y; }

// ============================================================
// conv1: x[512,256,24] -> relu -> maxpool2 -> g_h1[512][64][128]
// ============================================================
__global__ void __launch_bounds__(256) conv1_kernel(const float* __restrict__ x,
                                                    const float* __restrict__ w,
                                                    const float* __restrict__ bias)
{
    extern __shared__ float sm[];
    float* xs = sm;               // [24][260], col = t+2 (pad 2 each side)
    float* ws = sm + 24*260;      // [(f*5+k)][64]
    float* bs = ws + 7680;        // [64]
    const int b = blockIdx.x, tid = threadIdx.x;

    for (int idx = tid; idx < 6144; idx += 256){
        int t = idx / 24, f = idx % 24;
        xs[f*260 + t + 2] = x[b*6144 + idx];
    }
    for (int idx = tid; idx < 7680; idx += 256){
        int c = idx / 120, r = idx % 120;   // r = f*5+k
        ws[r*64 + c] = w[idx];
    }
    if (tid < 64) bs[tid] = bias[tid];
    if (tid < 96){  // zero the pad columns 0,1,258,259
        int f = tid >> 2, p = tid & 3;
        int col = (p < 2) ? p : (256 + p);
        xs[f*260 + col] = 0.f;
    }
    __syncthreads();

    const int c = tid & 63, seg = tid >> 6;
    const float bv = bs[c];
    for (int sub = 0; sub < 2; ++sub){
        const int tbase = seg*64 + sub*32;  // pre-pool start
        float acc[32];
        #pragma unroll
        for (int jj = 0; jj < 32; ++jj) acc[jj] = 0.f;
        for (int f = 0; f < 24; ++f){
            float wr[5];
            #pragma unroll
            for (int k = 0; k < 5; ++k) wr[k] = ws[(f*5+k)*64 + c];
            float xr[36];
            #pragma unroll
            for (int ii = 0; ii < 36; ++ii) xr[ii] = xs[f*260 + tbase + ii];
            #pragma unroll
            for (int jj = 0; jj < 32; ++jj){
                float a = acc[jj];
                #pragma unroll
                for (int k = 0; k < 5; ++k) a = fmaf(wr[k], xr[jj+k], a);
                acc[jj] = a;
            }
        }
        const int tp0 = tbase >> 1;
        #pragma unroll
        for (int m = 0; m < 16; ++m){
            float v = fmaxf(fmaxf(acc[2*m], acc[2*m+1]) + bv, 0.f);
            g_h1[(b*64 + c)*128 + tp0 + m] = v;
        }
    }
}

// ============================================================
// conv2: g_h1 -> relu -> maxpool2 -> g_feats[t'][b][cout]
// ============================================================
__global__ void __launch_bounds__(128) conv2_kernel(const float* __restrict__ w,
                                                    const float* __restrict__ bias)
{
    extern __shared__ float sm[];
    float* xs = sm;                 // [64][130], col = t+1 (pad 1 each side)
    float* ws = sm + 64*130;        // [(cin*3+k)][128]
    float* bs = ws + 24576;         // [128]
    const int b = blockIdx.x, tid = threadIdx.x;

    for (int idx = tid; idx < 8192; idx += 128){
        int cin = idx >> 7, t = idx & 127;
        xs[cin*130 + t + 1] = g_h1[b*8192 + idx];
    }
    for (int idx = tid; idx < 24576; idx += 128){
        int co = idx / 192, r = idx % 192;  // r = cin*3+k
        ws[r*128 + co] = w[idx];
    }
    bs[tid] = bias[tid];
    { int cin = tid >> 1, p = tid & 1; xs[cin*130 + (p ? 129 : 0)] = 0.f; }
    __syncthreads();

    const int co = tid;
    const float bv = bs[co];
    for (int chunk = 0; chunk < 4; ++chunk){
        const int tbase = chunk*32;
        float acc[32];
        #pragma unroll
        for (int jj = 0; jj < 32; ++jj) acc[jj] = 0.f;
        for (int cin = 0; cin < 64; ++cin){
            float wr[3];
            #pragma unroll
            for (int k = 0; k < 3; ++k) wr[k] = ws[(cin*3+k)*128 + co];
            float xr[34];
            #pragma unroll
            for (int ii = 0; ii < 34; ++ii) xr[ii] = xs[cin*130 + tbase + ii];
            #pragma unroll
            for (int jj = 0; jj < 32; ++jj){
                float a = acc[jj];
                #pragma unroll
                for (int k = 0; k < 3; ++k) a = fmaf(wr[k], xr[jj+k], a);
                acc[jj] = a;
            }
        }
        const int tp0 = chunk*16;
        #pragma unroll
        for (int m = 0; m < 16; ++m){
            float v = fmaxf(fmaxf(acc[2*m], acc[2*m+1]) + bv, 0.f);
            g_feats[((tp0 + m)*512 + b)*128 + co] = v;
        }
    }
}

// ============================================================
// sensory: for all (t',b) pairs compute w_num_s / w_den_s
// sigmoid((x-mu)*sig) = 1 / (1 + 2^( x*(-sig*log2e) + mu*sig*log2e ))
// ============================================================
__global__ void __launch_bounds__(256) sensory_kernel(
    const float* __restrict__ smu, const float* __restrict__ ssig,
    const float* __restrict__ sW,  const float* __restrict__ serev,
    const float* __restrict__ iw,  const float* __restrict__ ib)
{
    extern __shared__ float sm[];
    float* sP  = sm;               // 16384
    float* sQ  = sP + 16384;
    float* sH  = sQ + 16384;
    float* xts = sH + 16384;       // [4][128] staged inputs
    float* siw = xts + 512;        // [128]
    float* sib = siw + 128;        // [128]
    const int tid = threadIdx.x;

    for (int idx = tid; idx < 16384; idx += 256){
        float sg = ssig[idx];
        sP[idx] = -sg * LOG2E;
        sQ[idx] = smu[idx] * sg * LOG2E;
        sH[idx] = sW[idx] * serev[idx];   // |H| = W since erev = +-1, W>0
    }
    if (tid < 128){ siw[tid] = iw[tid]; sib[tid] = ib[tid]; }
    __syncthreads();

    const int j = tid & 127, pg = tid >> 7;
    const float* xa = xts + pg*256;
    const float* xb = xa + 128;

    // total pairs = 64*512 = 32768; grid 128 -> 256 pairs/CTA, 4 per iter
    for (int cc = 0; cc < 64; ++cc){
        const int qbase = blockIdx.x*256 + cc*4;    // q = t*512 + b
        for (int idx = tid; idx < 512; idx += 256){
            int pp = idx >> 7, i = idx & 127;
            xts[idx] = fmaf(g_feats[(qbase+pp)*128 + i], siw[i], sib[i]);
        }
        __syncthreads();
        float n0=0.f, d0=0.f, n1=0.f, d1=0.f;
        #pragma unroll 8
        for (int i = 0; i < 128; ++i){
            float p  = sP[(i<<7) + j];
            float qv = sQ[(i<<7) + j];
            float h  = sH[(i<<7) + j];
            float ha = fabsf(h);
            float s0 = fast_rcp(1.f + fast_ex2(fmaf(xa[i], p, qv)));
            float s1 = fast_rcp(1.f + fast_ex2(fmaf(xb[i], p, qv)));
            n0 = fmaf(h, s0, n0);  d0 = fmaf(ha, s0, d0);
            n1 = fmaf(h, s1, n1);  d1 = fmaf(ha, s1, d1);
        }
        const int qa = qbase + pg*2;
        g_wns[qa*128 + j]     = n0;
        g_wds[qa*128 + j]     = d0;
        g_wns[(qa+1)*128 + j] = n1;
        g_wds[(qa+1)*128 + j] = d1;
        __syncthreads();
    }
}

// ============================================================
// LTC recurrence: each CTA owns 4 batch rows for all 64 steps x 6 unfolds
// ============================================================
__global__ void __launch_bounds__(256) rec_kernel(
    const float* __restrict__ mu,    const float* __restrict__ sigma,
    const float* __restrict__ W,     const float* __restrict__ erev,
    const float* __restrict__ vleak, const float* __restrict__ gleak,
    const float* __restrict__ cmt)
{
    extern __shared__ float sm[];
    float* rP = sm;
    float* rQ = rP + 16384;
    float* rH = rQ + 16384;
    float* sV = rH + 16384;   // [4][128]
    const int tid = threadIdx.x;

    for (int idx = tid; idx < 16384; idx += 256){
        float sg = sigma[idx];
        rP[idx] = -sg * LOG2E;
        rQ[idx] = mu[idx] * sg * LOG2E;
        rH[idx] = W[idx] * erev[idx];
    }
    for (int idx = tid; idx < 512; idx += 256) sV[idx] = 0.f;

    const int j  = tid & 127, rg = tid >> 7;
    const int r0 = rg*2, r1 = rg*2 + 1;
    const float cmv = cmt[j];
    const float gl  = gleak[j];
    const float gv  = gl * vleak[j];
    const float cg  = cmv + gl;
    const int bbase = blockIdx.x * 4;
    float* v0p = sV + r0*128;
    float* v1p = sV + r1*128;
    __syncthreads();

    for (int t = 0; t < 64; ++t){
        const int base = t*512 + bbase;
        const float sn0 = g_wns[(base+r0)*128 + j];
        const float sd0 = g_wds[(base+r0)*128 + j];
        const float sn1 = g_wns[(base+r1)*128 + j];
        const float sd1 = g_wds[(base+r1)*128 + j];
        for (int u = 0; u < 6; ++u){
            float n0=sn0, d0=sd0, n1=sn1, d1=sd1;
            #pragma unroll 8
            for (int i = 0; i < 128; ++i){
                float p  = rP[(i<<7) + j];
                float qv = rQ[(i<<7) + j];
                float h  = rH[(i<<7) + j];
                float ha = fabsf(h);
                float s0 = fast_rcp(1.f + fast_ex2(fmaf(v0p[i], p, qv)));
                float s1 = fast_rcp(1.f + fast_ex2(fmaf(v1p[i], p, qv)));
                n0 = fmaf(h, s0, n0);  d0 = fmaf(ha, s0, d0);
                n1 = fmaf(h, s1, n1);  d1 = fmaf(ha, s1, d1);
            }
            float nv0 = (fmaf(cmv, v0p[j], gv) + n0) * fast_rcp(cg + d0);
            float nv1 = (fmaf(cmv, v1p[j], gv) + n1) * fast_rcp(cg + d1);
            __syncthreads();
            v0p[j] = nv0;
            v1p[j] = nv1;
            __syncthreads();
        }
    }
    g_hT[(bbase + r0)*128 + j] = v0p[j];
    g_hT[(bbase + r1)*128 + j] = v1p[j];
}

// ============================================================
// head: relu(hT @ fc1^T + b1) @ fc2^T + b2  -> out[512]
// ============================================================
__global__ void __launch_bounds__(64) head_kernel(
    const float* __restrict__ fc1w, const float* __restrict__ fc1b,
    const float* __restrict__ fc2w, const float* __restrict__ fc2b,
    float* __restrict__ out)
{
    __shared__ float sh[128];
    __shared__ float part[2];
    const int b = blockIdx.x, d = threadIdx.x;
    sh[d]      = g_hT[b*128 + d];
    sh[d + 64] = g_hT[b*128 + 64 + d];
    __syncthreads();
    float acc = fc1b[d];
    #pragma unroll 16
    for (int k = 0; k < 128; ++k)
        acc = fmaf(fc1w[d*128 + k], sh[k], acc);
    acc = fmaxf(acc, 0.f) * fc2w[d];
    #pragma unroll
    for (int off = 16; off > 0; off >>= 1)
        acc += __shfl_down_sync(0xffffffffu, acc, off);
    if ((d & 31) == 0) part[d >> 5] = acc;
    __syncthreads();
    if (d == 0) out[b] = part[0] + part[1] + fc2b[0];
}

extern "C" void kernel_launch(void* const* d_in, const int* in_sizes, int n_in,
                              void* d_out, int out_size)
{
    const float* x     = (const float*)d_in[0];
    const float* c1w   = (const float*)d_in[1];
    const float* c1b   = (const float*)d_in[2];
    const float* c2w   = (const float*)d_in[3];
    const float* c2b   = (const float*)d_in[4];
    const float* iw    = (const float*)d_in[5];
    const float* ib    = (const float*)d_in[6];
    const float* smu   = (const float*)d_in[7];
    const float* ssig  = (const float*)d_in[8];
    const float* sW    = (const float*)d_in[9];
    const float* serev = (const float*)d_in[10];
    const float* mu    = (const float*)d_in[11];
    const float* sigma = (const float*)d_in[12];
    const float* W     = (const float*)d_in[13];
    const float* erev  = (const float*)d_in[14];
    const float* vleak = (const float*)d_in[15];
    const float* gleak = (const float*)d_in[16];
    const float* cmt   = (const float*)d_in[17];
    const float* fc1w  = (const float*)d_in[18];
    const float* fc1b  = (const float*)d_in[19];
    const float* fc2w  = (const float*)d_in[20];
    const float* fc2b  = (const float*)d_in[21];
    float* out = (float*)d_out;

    const int SM_C1 = (24*260 + 7680 + 64) * 4;          //  55,936 B
    const int SM_C2 = (64*130 + 24576 + 128) * 4;        // 132,096 B
    const int SM_SE = (3*16384 + 512 + 256) * 4;         // 199,680 B
    const int SM_RE = (3*16384 + 512) * 4;               // 198,656 B
    cudaFuncSetAttribute(conv1_kernel,   cudaFuncAttributeMaxDynamicSharedMemorySize, SM_C1);
    cudaFuncSetAttribute(conv2_kernel,   cudaFuncAttributeMaxDynamicSharedMemorySize, SM_C2);
    cudaFuncSetAttribute(sensory_kernel, cudaFuncAttributeMaxDynamicSharedMemorySize, SM_SE);
    cudaFuncSetAttribute(rec_kernel,     cudaFuncAttributeMaxDynamicSharedMemorySize, SM_RE);

    conv1_kernel<<<512, 256, SM_C1>>>(x, c1w, c1b);
    conv2_kernel<<<512, 128, SM_C2>>>(c2w, c2b);
    sensory_kernel<<<128, 256, SM_SE>>>(smu, ssig, sW, serev, iw, ib);
    rec_kernel<<<128, 256, SM_RE>>>(mu, sigma, W, erev, vleak, gleak, cmt);
    head_kernel<<<512, 64>>>(fc1w, fc1b, fc2w, fc2b, out);
}

// round 2
// speedup vs baseline: 1.5163x; 1.5163x over previous
#include <cuda_runtime.h>

// ---- scratch (static __device__; no allocations allowed) ----
__device__ float g_h1[512*64*128];      // conv1 output   [b][c=64][t=128]
__device__ float g_feats[64*512*128];   // conv2 output   [t'=64][b][in=128]
__device__ float g_wns[64*512*128];     // sensory num    [t'][b][u]
__device__ float g_wds[64*512*128];     // sensory den    [t'][b][u]
__device__ float g_hT[512*128];         // final LTC state

__device__ __forceinline__ float fast_tanh(float x){ float y; asm("tanh.approx.f32 %0, %1;" : "=f"(y) : "f"(x)); return y; }
__device__ __forceinline__ float fast_rcp(float x){ float y; asm("rcp.approx.f32 %0, %1;" : "=f"(y) : "f"(x)); return y; }

// ============================================================
// conv1: x[512,256,24] -> relu -> maxpool2 -> g_h1[512][64][128]
// ============================================================
__global__ void __launch_bounds__(256) conv1_kernel(const float* __restrict__ x,
                                                    const float* __restrict__ w,
                                                    const float* __restrict__ bias)
{
    extern __shared__ float sm[];
    float* xs = sm;               // [24][260], col = t+2 (pad 2 each side)
    float* ws = sm + 24*260;      // [(f*5+k)][64]
    float* bs = ws + 7680;        // [64]
    const int b = blockIdx.x, tid = threadIdx.x;

    for (int idx = tid; idx < 6144; idx += 256){
        int t = idx / 24, f = idx % 24;
        xs[f*260 + t + 2] = x[b*6144 + idx];
    }
    for (int idx = tid; idx < 7680; idx += 256){
        int c = idx / 120, r = idx % 120;   // r = f*5+k
        ws[r*64 + c] = w[idx];
    }
    if (tid < 64) bs[tid] = bias[tid];
    if (tid < 96){  // zero the pad columns 0,1,258,259
        int f = tid >> 2, p = tid & 3;
        int col = (p < 2) ? p : (256 + p);
        xs[f*260 + col] = 0.f;
    }
    __syncthreads();

    const int c = tid & 63, seg = tid >> 6;
    const float bv = bs[c];
    for (int sub = 0; sub < 2; ++sub){
        const int tbase = seg*64 + sub*32;  // pre-pool start
        float acc[32];
        #pragma unroll
        for (int jj = 0; jj < 32; ++jj) acc[jj] = 0.f;
        for (int f = 0; f < 24; ++f){
            float wr[5];
            #pragma unroll
            for (int k = 0; k < 5; ++k) wr[k] = ws[(f*5+k)*64 + c];
            float xr[36];
            #pragma unroll
            for (int ii = 0; ii < 36; ++ii) xr[ii] = xs[f*260 + tbase + ii];
            #pragma unroll
            for (int jj = 0; jj < 32; ++jj){
                float a = acc[jj];
                #pragma unroll
                for (int k = 0; k < 5; ++k) a = fmaf(wr[k], xr[jj+k], a);
                acc[jj] = a;
            }
        }
        const int tp0 = tbase >> 1;
        #pragma unroll
        for (int m = 0; m < 16; ++m){
            float v = fmaxf(fmaxf(acc[2*m], acc[2*m+1]) + bv, 0.f);
            g_h1[(b*64 + c)*128 + tp0 + m] = v;
        }
    }
}

// ============================================================
// conv2: g_h1 -> relu -> maxpool2 -> g_feats[t'][b][cout]   (256 threads)
// ============================================================
__global__ void __launch_bounds__(256) conv2_kernel(const float* __restrict__ w,
                                                    const float* __restrict__ bias)
{
    extern __shared__ float sm[];
    float* xs = sm;                 // [64][130], col = t+1 (pad 1 each side)
    float* ws = sm + 64*130;        // [(cin*3+k)][128]
    float* bs = ws + 24576;         // [128]
    const int b = blockIdx.x, tid = threadIdx.x;

    for (int idx = tid; idx < 8192; idx += 256){
        int cin = idx >> 7, t = idx & 127;
        xs[cin*130 + t + 1] = g_h1[b*8192 + idx];
    }
    for (int idx = tid; idx < 24576; idx += 256){
        int co = idx / 192, r = idx % 192;  // r = cin*3+k
        ws[r*128 + co] = w[idx];
    }
    if (tid < 128) bs[tid] = bias[tid];
    if (tid < 128){ int cin = tid >> 1, p = tid & 1; xs[cin*130 + (p ? 129 : 0)] = 0.f; }
    __syncthreads();

    const int co = tid & 127, half = tid >> 7;
    const float bv = bs[co];
    for (int c2 = 0; c2 < 2; ++c2){
        const int chunk = half*2 + c2;
        const int tbase = chunk*32;
        float acc[32];
        #pragma unroll
        for (int jj = 0; jj < 32; ++jj) acc[jj] = 0.f;
        for (int cin = 0; cin < 64; ++cin){
            float wr[3];
            #pragma unroll
            for (int k = 0; k < 3; ++k) wr[k] = ws[(cin*3+k)*128 + co];
            float xr[34];
            #pragma unroll
            for (int ii = 0; ii < 34; ++ii) xr[ii] = xs[cin*130 + tbase + ii];
            #pragma unroll
            for (int jj = 0; jj < 32; ++jj){
                float a = acc[jj];
                #pragma unroll
                for (int k = 0; k < 3; ++k) a = fmaf(wr[k], xr[jj+k], a);
                acc[jj] = a;
            }
        }
        const int tp0 = chunk*16;
        #pragma unroll
        for (int m = 0; m < 16; ++m){
            float v = fmaxf(fmaxf(acc[2*m], acc[2*m+1]) + bv, 0.f);
            g_feats[((tp0 + m)*512 + b)*128 + co] = v;
        }
    }
}

// ============================================================
// sensory: for all (t',b) pairs compute w_num_s / w_den_s
// sigmoid((x-mu)*sig) = 0.5*tanh((x-mu)*sig*0.5) + 0.5
// sum W*erev*sig = sum h2*tanh + sum h2, with h2 = 0.5*W*erev
// ============================================================
__global__ void __launch_bounds__(256) sensory_kernel(
    const float* __restrict__ smu, const float* __restrict__ ssig,
    const float* __restrict__ sW,  const float* __restrict__ serev,
    const float* __restrict__ iw,  const float* __restrict__ ib)
{
    extern __shared__ float sm[];
    float2* sPQ = (float2*)sm;         // [16384] (128KB)
    float*  sH  = sm + 32768;          // [16384] h2
    float*  hsum  = sH + 16384;        // [128]
    float*  hasum = hsum + 128;        // [128]
    float*  xts   = hasum + 128;       // [4][128]
    float*  siw   = xts + 512;         // [128]
    float*  sib   = siw + 128;         // [128]
    const int tid = threadIdx.x;

    for (int idx = tid; idx < 16384; idx += 256){
        float sg = ssig[idx] * 0.5f;
        sPQ[idx] = make_float2(sg, -smu[idx] * sg);
        sH[idx]  = 0.5f * sW[idx] * serev[idx];
    }
    if (tid < 128){ siw[tid] = iw[tid]; sib[tid] = ib[tid]; }
    __syncthreads();
    if (tid < 128){
        float a = 0.f, bb = 0.f;
        for (int i = 0; i < 128; ++i){ float h = sH[(i<<7)+tid]; a += h; bb += fabsf(h); }
        hsum[tid] = a; hasum[tid] = bb;
    }
    __syncthreads();

    const int j = tid & 127, pg = tid >> 7;
    const float hs = hsum[j], has = hasum[j];
    const float* xa = xts + pg*256;
    const float* xb = xa + 128;

    // total pairs = 64*512 = 32768; grid 128 -> 256 pairs/CTA, 4 per iter
    for (int cc = 0; cc < 64; ++cc){
        const int qbase = blockIdx.x*256 + cc*4;    // q = t*512 + b
        for (int idx = tid; idx < 512; idx += 256){
            int pp = idx >> 7, i = idx & 127;
            xts[idx] = fmaf(g_feats[(qbase+pp)*128 + i], siw[i], sib[i]);
        }
        __syncthreads();
        float n0=0.f, d0=0.f, n1=0.f, d1=0.f;
        #pragma unroll 8
        for (int i = 0; i < 128; ++i){
            float2 P = sPQ[(i<<7) + j];
            float h  = sH[(i<<7) + j];
            float ha = fabsf(h);
            float t0 = fast_tanh(fmaf(xa[i], P.x, P.y));
            float t1 = fast_tanh(fmaf(xb[i], P.x, P.y));
            n0 = fmaf(h, t0, n0);  d0 = fmaf(ha, t0, d0);
            n1 = fmaf(h, t1, n1);  d1 = fmaf(ha, t1, d1);
        }
        const int qa = qbase + pg*2;
        g_wns[qa*128 + j]     = n0 + hs;
        g_wds[qa*128 + j]     = d0 + has;
        g_wns[(qa+1)*128 + j] = n1 + hs;
        g_wds[(qa+1)*128 + j] = d1 + has;
        __syncthreads();
    }
}

// ============================================================
// LTC recurrence: each CTA owns 4 batch rows for all 64 steps x 6 unfolds
// ping-pong v buffers, 1 named barrier per unfold per 128-thread group
// ============================================================
__global__ void __launch_bounds__(256) rec_kernel(
    const float* __restrict__ mu,    const float* __restrict__ sigma,
    const float* __restrict__ W,     const float* __restrict__ erev,
    const float* __restrict__ vleak, const float* __restrict__ gleak,
    const float* __restrict__ cmt)
{
    extern __shared__ float sm[];
    float2* rPQ = (float2*)sm;         // [16384]
    float*  rH  = sm + 32768;          // [16384] h2 = 0.5*W*erev
    float*  hsum  = rH + 16384;        // [128]
    float*  hasum = hsum + 128;        // [128]
    float*  sV    = hasum + 128;       // [2][4][128] ping-pong
    const int tid = threadIdx.x;

    for (int idx = tid; idx < 16384; idx += 256){
        float sg = sigma[idx] * 0.5f;
        rPQ[idx] = make_float2(sg, -mu[idx] * sg);
        rH[idx]  = 0.5f * W[idx] * erev[idx];
    }
    for (int idx = tid; idx < 512; idx += 256) sV[idx] = 0.f;
    __syncthreads();
    if (tid < 128){
        float a = 0.f, bb = 0.f;
        for (int i = 0; i < 128; ++i){ float h = rH[(i<<7)+tid]; a += h; bb += fabsf(h); }
        hsum[tid] = a; hasum[tid] = bb;
    }
    __syncthreads();

    const int j  = tid & 127, rg = tid >> 7;
    const int r0 = rg*2;
    const float cmv = cmt[j];
    const float gl  = gleak[j];
    const float base_n = gl * vleak[j] + hsum[j];
    const float base_d = cmv + gl + hasum[j];
    const int bbase = blockIdx.x * 4;
    const int barid = rg + 1;
    int pp = 0;

    for (int t = 0; t < 64; ++t){
        const int base = t*512 + bbase + r0;
        const float c_n0 = base_n + g_wns[base*128 + j];
        const float c_d0 = base_d + g_wds[base*128 + j];
        const float c_n1 = base_n + g_wns[(base+1)*128 + j];
        const float c_d1 = base_d + g_wds[(base+1)*128 + j];
        for (int u = 0; u < 6; ++u){
            const float* va = sV + pp*512 + r0*128;
            const float* vb = va + 128;
            float n0=0.f, d0=0.f, n1=0.f, d1=0.f;
            #pragma unroll 8
            for (int i = 0; i < 128; ++i){
                float2 P = rPQ[(i<<7) + j];
                float h  = rH[(i<<7) + j];
                float ha = fabsf(h);
                float t0 = fast_tanh(fmaf(va[i], P.x, P.y));
                float t1 = fast_tanh(fmaf(vb[i], P.x, P.y));
                n0 = fmaf(h, t0, n0);  d0 = fmaf(ha, t0, d0);
                n1 = fmaf(h, t1, n1);  d1 = fmaf(ha, t1, d1);
            }
            float nv0 = (fmaf(cmv, va[j], c_n0) + n0) * fast_rcp(c_d0 + d0);
            float nv1 = (fmaf(cmv, vb[j], c_n1) + n1) * fast_rcp(c_d1 + d1);
            float* wv = sV + (pp^1)*512 + r0*128;
            wv[j]       = nv0;
            wv[128 + j] = nv1;
            pp ^= 1;
            asm volatile("bar.sync %0, %1;" :: "r"(barid), "r"(128) : "memory");
        }
    }
    const float* vf = sV + pp*512 + r0*128;
    g_hT[(bbase + r0)*128 + j]     = vf[j];
    g_hT[(bbase + r0 + 1)*128 + j] = vf[128 + j];
}

// ============================================================
// head: relu(hT @ fc1^T + b1) @ fc2^T + b2  -> out[512]
// ============================================================
__global__ void __launch_bounds__(64) head_kernel(
    const float* __restrict__ fc1w, const float* __restrict__ fc1b,
    const float* __restrict__ fc2w, const float* __restrict__ fc2b,
    float* __restrict__ out)
{
    __shared__ float sh[128];
    __shared__ float part[2];
    const int b = blockIdx.x, d = threadIdx.x;
    sh[d]      = g_hT[b*128 + d];
    sh[d + 64] = g_hT[b*128 + 64 + d];
    __syncthreads();
    float acc = fc1b[d];
    #pragma unroll 16
    for (int k = 0; k < 128; ++k)
        acc = fmaf(fc1w[d*128 + k], sh[k], acc);
    acc = fmaxf(acc, 0.f) * fc2w[d];
    #pragma unroll
    for (int off = 16; off > 0; off >>= 1)
        acc += __shfl_down_sync(0xffffffffu, acc, off);
    if ((d & 31) == 0) part[d >> 5] = acc;
    __syncthreads();
    if (d == 0) out[b] = part[0] + part[1] + fc2b[0];
}

extern "C" void kernel_launch(void* const* d_in, const int* in_sizes, int n_in,
                              void* d_out, int out_size)
{
    const float* x     = (const float*)d_in[0];
    const float* c1w   = (const float*)d_in[1];
    const float* c1b   = (const float*)d_in[2];
    const float* c2w   = (const float*)d_in[3];
    const float* c2b   = (const float*)d_in[4];
    const float* iw    = (const float*)d_in[5];
    const float* ib    = (const float*)d_in[6];
    const float* smu   = (const float*)d_in[7];
    const float* ssig  = (const float*)d_in[8];
    const float* sW    = (const float*)d_in[9];
    const float* serev = (const float*)d_in[10];
    const float* mu    = (const float*)d_in[11];
    const float* sigma = (const float*)d_in[12];
    const float* W     = (const float*)d_in[13];
    const float* erev  = (const float*)d_in[14];
    const float* vleak = (const float*)d_in[15];
    const float* gleak = (const float*)d_in[16];
    const float* cmt   = (const float*)d_in[17];
    const float* fc1w  = (const float*)d_in[18];
    const float* fc1b  = (const float*)d_in[19];
    const float* fc2w  = (const float*)d_in[20];
    const float* fc2b  = (const float*)d_in[21];
    float* out = (float*)d_out;

    const int SM_C1 = (24*260 + 7680 + 64) * 4;                       //  55,936 B
    const int SM_C2 = (64*130 + 24576 + 128) * 4;                     // 132,096 B
    const int SM_SE = (32768 + 16384 + 256 + 512 + 256) * 4;          // 200,704 B
    const int SM_RE = (32768 + 16384 + 256 + 1024) * 4;               // 201,728 B
    cudaFuncSetAttribute(conv1_kernel,   cudaFuncAttributeMaxDynamicSharedMemorySize, SM_C1);
    cudaFuncSetAttribute(conv2_kernel,   cudaFuncAttributeMaxDynamicSharedMemorySize, SM_C2);
    cudaFuncSetAttribute(sensory_kernel, cudaFuncAttributeMaxDynamicSharedMemorySize, SM_SE);
    cudaFuncSetAttribute(rec_kernel,     cudaFuncAttributeMaxDynamicSharedMemorySize, SM_RE);

    conv1_kernel<<<512, 256, SM_C1>>>(x, c1w, c1b);
    conv2_kernel<<<512, 256, SM_C2>>>(c2w, c2b);
    sensory_kernel<<<128, 256, SM_SE>>>(smu, ssig, sW, serev, iw, ib);
    rec_kernel<<<128, 256, SM_RE>>>(mu, sigma, W, erev, vleak, gleak, cmt);
    head_kernel<<<512, 64>>>(fc1w, fc1b, fc2w, fc2b, out);
}

// round 3
// speedup vs baseline: 1.6410x; 1.0822x over previous
#include <cuda_runtime.h>

// ---- scratch (static __device__; no allocations allowed) ----
__device__ float g_h1[512*64*128];      // conv1 output   [b][c=64][t=128]
__device__ float g_feats[64*512*128];   // conv2 output   [t'=64][b][in=128]
__device__ float g_wns[64*512*128];     // sensory num    [t'][b][u]
__device__ float g_wds[64*512*128];     // sensory den    [t'][b][u]
__device__ float g_hT[512*128];         // final LTC state

__device__ __forceinline__ float fast_tanh(float x){ float y; asm("tanh.approx.f32 %0, %1;" : "=f"(y) : "f"(x)); return y; }
__device__ __forceinline__ float fast_rcp(float x){ float y; asm("rcp.approx.f32 %0, %1;" : "=f"(y) : "f"(x)); return y; }

// ============================================================
// conv1: x[512,256,24] -> relu -> maxpool2 -> g_h1[512][64][128]
// ============================================================
__global__ void __launch_bounds__(256) conv1_kernel(const float* __restrict__ x,
                                                    const float* __restrict__ w,
                                                    const float* __restrict__ bias)
{
    extern __shared__ float sm[];
    float* xs = sm;               // [24][260], col = t+2 (pad 2 each side)
    float* ws = sm + 24*260;      // [(f*5+k)][64]
    float* bs = ws + 7680;        // [64]
    const int b = blockIdx.x, tid = threadIdx.x;

    for (int idx = tid; idx < 6144; idx += 256){
        int t = idx / 24, f = idx % 24;
        xs[f*260 + t + 2] = x[b*6144 + idx];
    }
    for (int idx = tid; idx < 7680; idx += 256){
        int c = idx / 120, r = idx % 120;   // r = f*5+k
        ws[r*64 + c] = w[idx];
    }
    if (tid < 64) bs[tid] = bias[tid];
    if (tid < 96){  // zero the pad columns 0,1,258,259
        int f = tid >> 2, p = tid & 3;
        int col = (p < 2) ? p : (256 + p);
        xs[f*260 + col] = 0.f;
    }
    __syncthreads();

    const int c = tid & 63, seg = tid >> 6;
    const float bv = bs[c];
    for (int sub = 0; sub < 2; ++sub){
        const int tbase = seg*64 + sub*32;  // pre-pool start
        float acc[32];
        #pragma unroll
        for (int jj = 0; jj < 32; ++jj) acc[jj] = 0.f;
        for (int f = 0; f < 24; ++f){
            float wr[5];
            #pragma unroll
            for (int k = 0; k < 5; ++k) wr[k] = ws[(f*5+k)*64 + c];
            float xr[36];
            #pragma unroll
            for (int ii = 0; ii < 36; ++ii) xr[ii] = xs[f*260 + tbase + ii];
            #pragma unroll
            for (int jj = 0; jj < 32; ++jj){
                float a = acc[jj];
                #pragma unroll
                for (int k = 0; k < 5; ++k) a = fmaf(wr[k], xr[jj+k], a);
                acc[jj] = a;
            }
        }
        const int tp0 = tbase >> 1;
        #pragma unroll
        for (int m = 0; m < 16; ++m){
            float v = fmaxf(fmaxf(acc[2*m], acc[2*m+1]) + bv, 0.f);
            g_h1[(b*64 + c)*128 + tp0 + m] = v;
        }
    }
}

// ============================================================
// conv2: g_h1 -> relu -> maxpool2 -> g_feats[t'][b][cout]   (256 threads)
// ============================================================
__global__ void __launch_bounds__(256) conv2_kernel(const float* __restrict__ w,
                                                    const float* __restrict__ bias)
{
    extern __shared__ float sm[];
    float* xs = sm;                 // [64][130], col = t+1 (pad 1 each side)
    float* ws = sm + 64*130;        // [(cin*3+k)][128]
    float* bs = ws + 24576;         // [128]
    const int b = blockIdx.x, tid = threadIdx.x;

    for (int idx = tid; idx < 8192; idx += 256){
        int cin = idx >> 7, t = idx & 127;
        xs[cin*130 + t + 1] = g_h1[b*8192 + idx];
    }
    for (int idx = tid; idx < 24576; idx += 256){
        int co = idx / 192, r = idx % 192;  // r = cin*3+k
        ws[r*128 + co] = w[idx];
    }
    if (tid < 128) bs[tid] = bias[tid];
    if (tid < 128){ int cin = tid >> 1, p = tid & 1; xs[cin*130 + (p ? 129 : 0)] = 0.f; }
    __syncthreads();

    const int co = tid & 127, half = tid >> 7;
    const float bv = bs[co];
    for (int c2 = 0; c2 < 2; ++c2){
        const int chunk = half*2 + c2;
        const int tbase = chunk*32;
        float acc[32];
        #pragma unroll
        for (int jj = 0; jj < 32; ++jj) acc[jj] = 0.f;
        for (int cin = 0; cin < 64; ++cin){
            float wr[3];
            #pragma unroll
            for (int k = 0; k < 3; ++k) wr[k] = ws[(cin*3+k)*128 + co];
            float xr[34];
            #pragma unroll
            for (int ii = 0; ii < 34; ++ii) xr[ii] = xs[cin*130 + tbase + ii];
            #pragma unroll
            for (int jj = 0; jj < 32; ++jj){
                float a = acc[jj];
                #pragma unroll
                for (int k = 0; k < 3; ++k) a = fmaf(wr[k], xr[jj+k], a);
                acc[jj] = a;
            }
        }
        const int tp0 = chunk*16;
        #pragma unroll
        for (int m = 0; m < 16; ++m){
            float v = fmaxf(fmaxf(acc[2*m], acc[2*m+1]) + bv, 0.f);
            g_feats[((tp0 + m)*512 + b)*128 + co] = v;
        }
    }
}

// ============================================================
// sensory: all (t',b) pairs -> w_num_s / w_den_s
// 4 pairs per outer iter; threads split the i-range (64 each),
// partials combined through SMEM.
// ============================================================
__global__ void __launch_bounds__(256) sensory_kernel(
    const float* __restrict__ smu, const float* __restrict__ ssig,
    const float* __restrict__ sW,  const float* __restrict__ serev,
    const float* __restrict__ iw,  const float* __restrict__ ib)
{
    extern __shared__ float sm[];
    float2* sPQ = (float2*)sm;         // [16384]
    float*  sH  = sm + 32768;          // [16384] h2 = 0.5*W*erev
    float*  xts = sH + 16384;          // [4][128]
    float*  pn  = xts + 512;           // [4][128]
    float*  pd  = pn + 512;            // [4][128]
    float*  hsum  = pd + 512;          // [128]
    float*  hasum = hsum + 128;        // [128]
    float*  siw   = hasum + 128;       // [128]
    float*  sib   = siw + 128;         // [128]
    const int tid = threadIdx.x;

    for (int idx = tid; idx < 16384; idx += 256){
        float sg = ssig[idx] * 0.5f;
        sPQ[idx] = make_float2(sg, -smu[idx] * sg);
        sH[idx]  = 0.5f * sW[idx] * serev[idx];
    }
    if (tid < 128){ siw[tid] = iw[tid]; sib[tid] = ib[tid]; }
    __syncthreads();
    if (tid < 128){
        float a = 0.f, bb = 0.f;
        for (int i = 0; i < 128; ++i){ float h = sH[(i<<7)+tid]; a += h; bb += fabsf(h); }
        hsum[tid] = a; hasum[tid] = bb;
    }
    __syncthreads();

    const int j = tid & 127, half = tid >> 7;
    const int i0 = half << 6;
    const float hs = hsum[j], has = hasum[j];

    // total pairs = 64*512 = 32768; grid 128 -> 256 pairs/CTA, 4 per iter
    for (int cc = 0; cc < 64; ++cc){
        const int qbase = blockIdx.x*256 + cc*4;    // q = t*512 + b
        for (int idx = tid; idx < 512; idx += 256){
            int pp = idx >> 7, i = idx & 127;
            xts[idx] = fmaf(g_feats[(qbase+pp)*128 + i], siw[i], sib[i]);
        }
        __syncthreads();
        float n0=0.f,n1=0.f,n2=0.f,n3=0.f,d0=0.f,d1=0.f,d2=0.f,d3=0.f;
        #pragma unroll 8
        for (int ii = 0; ii < 64; ++ii){
            const int i = i0 + ii;
            float2 P = sPQ[(i<<7) + j];
            float h  = sH[(i<<7) + j];
            float ha = fabsf(h);
            float x0 = xts[i], x1 = xts[128+i], x2 = xts[256+i], x3 = xts[384+i];
            float t0 = fast_tanh(fmaf(x0, P.x, P.y));
            float t1 = fast_tanh(fmaf(x1, P.x, P.y));
            float t2 = fast_tanh(fmaf(x2, P.x, P.y));
            float t3 = fast_tanh(fmaf(x3, P.x, P.y));
            n0 = fmaf(h, t0, n0);  d0 = fmaf(ha, t0, d0);
            n1 = fmaf(h, t1, n1);  d1 = fmaf(ha, t1, d1);
            n2 = fmaf(h, t2, n2);  d2 = fmaf(ha, t2, d2);
            n3 = fmaf(h, t3, n3);  d3 = fmaf(ha, t3, d3);
        }
        if (half){
            pn[j] = n0; pn[128+j] = n1; pn[256+j] = n2; pn[384+j] = n3;
            pd[j] = d0; pd[128+j] = d1; pd[256+j] = d2; pd[384+j] = d3;
        }
        __syncthreads();
        if (!half){
            g_wns[(qbase+0)*128 + j] = n0 + pn[j]     + hs;
            g_wds[(qbase+0)*128 + j] = d0 + pd[j]     + has;
            g_wns[(qbase+1)*128 + j] = n1 + pn[128+j] + hs;
            g_wds[(qbase+1)*128 + j] = d1 + pd[128+j] + has;
            g_wns[(qbase+2)*128 + j] = n2 + pn[256+j] + hs;
            g_wds[(qbase+2)*128 + j] = d2 + pd[256+j] + has;
            g_wns[(qbase+3)*128 + j] = n3 + pn[384+j] + hs;
            g_wds[(qbase+3)*128 + j] = d3 + pd[384+j] + has;
        }
    }
}

// ============================================================
// LTC recurrence: CTA owns 4 batch rows; each thread accumulates
// all 4 rows over half the i-range; partials combined via SMEM.
// ============================================================
__global__ void __launch_bounds__(256) rec_kernel(
    const float* __restrict__ mu,    const float* __restrict__ sigma,
    const float* __restrict__ W,     const float* __restrict__ erev,
    const float* __restrict__ vleak, const float* __restrict__ gleak,
    const float* __restrict__ cmt)
{
    extern __shared__ float sm[];
    float2* rPQ = (float2*)sm;         // [16384]
    float*  rH  = sm + 32768;          // [16384] h2 = 0.5*W*erev
    float*  sV  = rH + 16384;          // [4][128]
    float*  pn  = sV + 512;            // [4][128]
    float*  pd  = pn + 512;            // [4][128]
    float*  hsum  = pd + 512;          // [128]
    float*  hasum = hsum + 128;        // [128]
    const int tid = threadIdx.x;

    for (int idx = tid; idx < 16384; idx += 256){
        float sg = sigma[idx] * 0.5f;
        rPQ[idx] = make_float2(sg, -mu[idx] * sg);
        rH[idx]  = 0.5f * W[idx] * erev[idx];
    }
    for (int idx = tid; idx < 512; idx += 256) sV[idx] = 0.f;
    __syncthreads();
    if (tid < 128){
        float a = 0.f, bb = 0.f;
        for (int i = 0; i < 128; ++i){ float h = rH[(i<<7)+tid]; a += h; bb += fabsf(h); }
        hsum[tid] = a; hasum[tid] = bb;
    }
    __syncthreads();

    const int j = tid & 127, half = tid >> 7;
    const int i0 = half << 6;
    const float cmv = cmt[j];
    const float gl  = gleak[j];
    const float base_n = gl * vleak[j] + hsum[j];
    const float base_d = cmv + gl + hasum[j];
    const int bbase = blockIdx.x * 4;

    for (int t = 0; t < 64; ++t){
        float c_n[4], c_d[4];
        if (!half){
            #pragma unroll
            for (int r = 0; r < 4; ++r){
                const int q = (t*512 + bbase + r)*128 + j;
                c_n[r] = base_n + g_wns[q];
                c_d[r] = base_d + g_wds[q];
            }
        }
        for (int u = 0; u < 6; ++u){
            float n0=0.f,n1=0.f,n2=0.f,n3=0.f,d0=0.f,d1=0.f,d2=0.f,d3=0.f;
            #pragma unroll 8
            for (int ii = 0; ii < 64; ++ii){
                const int i = i0 + ii;
                float2 P = rPQ[(i<<7) + j];
                float h  = rH[(i<<7) + j];
                float ha = fabsf(h);
                float v0 = sV[i], v1 = sV[128+i], v2 = sV[256+i], v3 = sV[384+i];
                float t0 = fast_tanh(fmaf(v0, P.x, P.y));
                float t1 = fast_tanh(fmaf(v1, P.x, P.y));
                float t2 = fast_tanh(fmaf(v2, P.x, P.y));
                float t3 = fast_tanh(fmaf(v3, P.x, P.y));
                n0 = fmaf(h, t0, n0);  d0 = fmaf(ha, t0, d0);
                n1 = fmaf(h, t1, n1);  d1 = fmaf(ha, t1, d1);
                n2 = fmaf(h, t2, n2);  d2 = fmaf(ha, t2, d2);
                n3 = fmaf(h, t3, n3);  d3 = fmaf(ha, t3, d3);
            }
            if (half){
                pn[j] = n0; pn[128+j] = n1; pn[256+j] = n2; pn[384+j] = n3;
                pd[j] = d0; pd[128+j] = d1; pd[256+j] = d2; pd[384+j] = d3;
            }
            __syncthreads();
            if (!half){
                float nv0 = (fmaf(cmv, sV[j],     c_n[0]) + n0 + pn[j])     * fast_rcp(c_d[0] + d0 + pd[j]);
                float nv1 = (fmaf(cmv, sV[128+j], c_n[1]) + n1 + pn[128+j]) * fast_rcp(c_d[1] + d1 + pd[128+j]);
                float nv2 = (fmaf(cmv, sV[256+j], c_n[2]) + n2 + pn[256+j]) * fast_rcp(c_d[2] + d2 + pd[256+j]);
                float nv3 = (fmaf(cmv, sV[384+j], c_n[3]) + n3 + pn[384+j]) * fast_rcp(c_d[3] + d3 + pd[384+j]);
                sV[j]     = nv0;
                sV[128+j] = nv1;
                sV[256+j] = nv2;
                sV[384+j] = nv3;
            }
            __syncthreads();
        }
    }
    if (!half){
        #pragma unroll
        for (int r = 0; r < 4; ++r)
            g_hT[(bbase + r)*128 + j] = sV[r*128 + j];
    }
}

// ============================================================
// head: relu(hT @ fc1^T + b1) @ fc2^T + b2  -> out[512]
// ============================================================
__global__ void __launch_bounds__(64) head_kernel(
    const float* __restrict__ fc1w, const float* __restrict__ fc1b,
    const float* __restrict__ fc2w, const float* __restrict__ fc2b,
    float* __restrict__ out)
{
    __shared__ float sh[128];
    __shared__ float part[2];
    const int b = blockIdx.x, d = threadIdx.x;
    sh[d]      = g_hT[b*128 + d];
    sh[d + 64] = g_hT[b*128 + 64 + d];
    __syncthreads();
    float acc = fc1b[d];
    #pragma unroll 16
    for (int k = 0; k < 128; ++k)
        acc = fmaf(fc1w[d*128 + k], sh[k], acc);
    acc = fmaxf(acc, 0.f) * fc2w[d];
    #pragma unroll
    for (int off = 16; off > 0; off >>= 1)
        acc += __shfl_down_sync(0xffffffffu, acc, off);
    if ((d & 31) == 0) part[d >> 5] = acc;
    __syncthreads();
    if (d == 0) out[b] = part[0] + part[1] + fc2b[0];
}

extern "C" void kernel_launch(void* const* d_in, const int* in_sizes, int n_in,
                              void* d_out, int out_size)
{
    const float* x     = (const float*)d_in[0];
    const float* c1w   = (const float*)d_in[1];
    const float* c1b   = (const float*)d_in[2];
    const float* c2w   = (const float*)d_in[3];
    const float* c2b   = (const float*)d_in[4];
    const float* iw    = (const float*)d_in[5];
    const float* ib    = (const float*)d_in[6];
    const float* smu   = (const float*)d_in[7];
    const float* ssig  = (const float*)d_in[8];
    const float* sW    = (const float*)d_in[9];
    const float* serev = (const float*)d_in[10];
    const float* mu    = (const float*)d_in[11];
    const float* sigma = (const float*)d_in[12];
    const float* W     = (const float*)d_in[13];
    const float* erev  = (const float*)d_in[14];
    const float* vleak = (const float*)d_in[15];
    const float* gleak = (const float*)d_in[16];
    const float* cmt   = (const float*)d_in[17];
    const float* fc1w  = (const float*)d_in[18];
    const float* fc1b  = (const float*)d_in[19];
    const float* fc2w  = (const float*)d_in[20];
    const float* fc2b  = (const float*)d_in[21];
    float* out = (float*)d_out;

    const int SM_C1 = (24*260 + 7680 + 64) * 4;                                 //  55,936 B
    const int SM_C2 = (64*130 + 24576 + 128) * 4;                               // 132,096 B
    const int SM_SE = (32768 + 16384 + 512 + 512 + 512 + 128 + 128 + 128 + 128) * 4; // 204,800 B
    const int SM_RE = (32768 + 16384 + 512 + 512 + 512 + 128 + 128) * 4;             // 203,776 B
    cudaFuncSetAttribute(conv1_kernel,   cudaFuncAttributeMaxDynamicSharedMemorySize, SM_C1);
    cudaFuncSetAttribute(conv2_kernel,   cudaFuncAttributeMaxDynamicSharedMemorySize, SM_C2);
    cudaFuncSetAttribute(sensory_kernel, cudaFuncAttributeMaxDynamicSharedMemorySize, SM_SE);
    cudaFuncSetAttribute(rec_kernel,     cudaFuncAttributeMaxDynamicSharedMemorySize, SM_RE);

    conv1_kernel<<<512, 256, SM_C1>>>(x, c1w, c1b);
    conv2_kernel<<<512, 256, SM_C2>>>(c2w, c2b);
    sensory_kernel<<<128, 256, SM_SE>>>(smu, ssig, sW, serev, iw, ib);
    rec_kernel<<<128, 256, SM_RE>>>(mu, sigma, W, erev, vleak, gleak, cmt);
    head_kernel<<<512, 64>>>(fc1w, fc1b, fc2w, fc2b, out);
}

// round 4
// speedup vs baseline: 1.8054x; 1.1002x over previous
#include <cuda_runtime.h>

// ---- scratch (static __device__; no allocations allowed) ----
__device__ float g_h1[512*64*128];      // conv1 output   [b][c=64][t=128]
__device__ float g_feats[64*512*128];   // conv2 output   [t'=64][b][in=128]
__device__ float g_wns[64*512*128];     // sensory num    [t'][b][u]
__device__ float g_wds[64*512*128];     // sensory den    [t'][b][u]
__device__ float g_hT[512*128];         // final LTC state

__device__ __forceinline__ float fast_tanh(float x){ float y; asm("tanh.approx.f32 %0, %1;" : "=f"(y) : "f"(x)); return y; }
__device__ __forceinline__ float fast_rcp(float x){ float y; asm("rcp.approx.f32 %0, %1;" : "=f"(y) : "f"(x)); return y; }

// ============================================================
// conv1: x[512,256,24] -> relu -> maxpool2 -> g_h1[512][64][128]
// ============================================================
__global__ void __launch_bounds__(256) conv1_kernel(const float* __restrict__ x,
                                                    const float* __restrict__ w,
                                                    const float* __restrict__ bias)
{
    extern __shared__ float sm[];
    float* xs = sm;               // [24][260], col = t+2 (pad 2 each side)
    float* ws = sm + 24*260;      // [(f*5+k)][64]
    float* bs = ws + 7680;        // [64]
    const int b = blockIdx.x, tid = threadIdx.x;

    for (int idx = tid; idx < 6144; idx += 256){
        int t = idx / 24, f = idx % 24;
        xs[f*260 + t + 2] = x[b*6144 + idx];
    }
    for (int idx = tid; idx < 7680; idx += 256){
        int c = idx / 120, r = idx % 120;   // r = f*5+k
        ws[r*64 + c] = w[idx];
    }
    if (tid < 64) bs[tid] = bias[tid];
    if (tid < 96){  // zero the pad columns 0,1,258,259
        int f = tid >> 2, p = tid & 3;
        int col = (p < 2) ? p : (256 + p);
        xs[f*260 + col] = 0.f;
    }
    __syncthreads();

    const int c = tid & 63, seg = tid >> 6;
    const float bv = bs[c];
    for (int sub = 0; sub < 2; ++sub){
        const int tbase = seg*64 + sub*32;  // pre-pool start
        float acc[32];
        #pragma unroll
        for (int jj = 0; jj < 32; ++jj) acc[jj] = 0.f;
        for (int f = 0; f < 24; ++f){
            float wr[5];
            #pragma unroll
            for (int k = 0; k < 5; ++k) wr[k] = ws[(f*5+k)*64 + c];
            float xr[36];
            #pragma unroll
            for (int ii = 0; ii < 36; ++ii) xr[ii] = xs[f*260 + tbase + ii];
            #pragma unroll
            for (int jj = 0; jj < 32; ++jj){
                float a = acc[jj];
                #pragma unroll
                for (int k = 0; k < 5; ++k) a = fmaf(wr[k], xr[jj+k], a);
                acc[jj] = a;
            }
        }
        const int tp0 = tbase >> 1;
        #pragma unroll
        for (int m = 0; m < 16; ++m){
            float v = fmaxf(fmaxf(acc[2*m], acc[2*m+1]) + bv, 0.f);
            g_h1[(b*64 + c)*128 + tp0 + m] = v;
        }
    }
}

// ============================================================
// conv2: g_h1 -> relu -> maxpool2 -> g_feats[t'][b][cout]   (256 threads)
// ============================================================
__global__ void __launch_bounds__(256) conv2_kernel(const float* __restrict__ w,
                                                    const float* __restrict__ bias)
{
    extern __shared__ float sm[];
    float* xs = sm;                 // [64][130], col = t+1 (pad 1 each side)
    float* ws = sm + 64*130;        // [(cin*3+k)][128]
    float* bs = ws + 24576;         // [128]
    const int b = blockIdx.x, tid = threadIdx.x;

    for (int idx = tid; idx < 8192; idx += 256){
        int cin = idx >> 7, t = idx & 127;
        xs[cin*130 + t + 1] = g_h1[b*8192 + idx];
    }
    for (int idx = tid; idx < 24576; idx += 256){
        int co = idx / 192, r = idx % 192;  // r = cin*3+k
        ws[r*128 + co] = w[idx];
    }
    if (tid < 128) bs[tid] = bias[tid];
    if (tid < 128){ int cin = tid >> 1, p = tid & 1; xs[cin*130 + (p ? 129 : 0)] = 0.f; }
    __syncthreads();

    const int co = tid & 127, half = tid >> 7;
    const float bv = bs[co];
    for (int c2 = 0; c2 < 2; ++c2){
        const int chunk = half*2 + c2;
        const int tbase = chunk*32;
        float acc[32];
        #pragma unroll
        for (int jj = 0; jj < 32; ++jj) acc[jj] = 0.f;
        for (int cin = 0; cin < 64; ++cin){
            float wr[3];
            #pragma unroll
            for (int k = 0; k < 3; ++k) wr[k] = ws[(cin*3+k)*128 + co];
            float xr[34];
            #pragma unroll
            for (int ii = 0; ii < 34; ++ii) xr[ii] = xs[cin*130 + tbase + ii];
            #pragma unroll
            for (int jj = 0; jj < 32; ++jj){
                float a = acc[jj];
                #pragma unroll
                for (int k = 0; k < 3; ++k) a = fmaf(wr[k], xr[jj+k], a);
                acc[jj] = a;
            }
        }
        const int tp0 = chunk*16;
        #pragma unroll
        for (int m = 0; m < 16; ++m){
            float v = fmaxf(fmaxf(acc[2*m], acc[2*m+1]) + bv, 0.f);
            g_feats[((tp0 + m)*512 + b)*128 + co] = v;
        }
    }
}

// ============================================================
// sensory: all (t',b) pairs -> w_num_s / w_den_s
// 512 threads: 4 quarters over the i-range, 4 pairs per iter.
// ============================================================
__global__ void __launch_bounds__(512) sensory_kernel(
    const float* __restrict__ smu, const float* __restrict__ ssig,
    const float* __restrict__ sW,  const float* __restrict__ serev,
    const float* __restrict__ iw,  const float* __restrict__ ib)
{
    extern __shared__ float sm[];
    float2* sPQ = (float2*)sm;         // [16384]
    float*  sH  = sm + 32768;          // [16384] h2 = 0.5*W*erev
    float*  xts = sH + 16384;          // [4][128]
    float*  pn  = xts + 512;           // [4 qt][4 pair][128]
    float*  pd  = pn + 2048;           // [4 qt][4 pair][128]
    float*  hsum  = pd + 2048;         // [128]
    float*  hasum = hsum + 128;        // [128]
    float*  siw   = hasum + 128;       // [128]
    float*  sib   = siw + 128;         // [128]
    const int tid = threadIdx.x;

    for (int idx = tid; idx < 16384; idx += 512){
        float sg = ssig[idx] * 0.5f;
        sPQ[idx] = make_float2(sg, -smu[idx] * sg);
        sH[idx]  = 0.5f * sW[idx] * serev[idx];
    }
    if (tid < 128){ siw[tid] = iw[tid]; sib[tid] = ib[tid]; }
    __syncthreads();
    if (tid < 128){
        float a = 0.f, bb = 0.f;
        for (int i = 0; i < 128; ++i){ float h = sH[(i<<7)+tid]; a += h; bb += fabsf(h); }
        hsum[tid] = a; hasum[tid] = bb;
    }
    __syncthreads();

    const int j = tid & 127, qt = tid >> 7;   // quarter 0..3
    const int i0 = qt << 5;
    const float hs = hsum[j], has = hasum[j];
    const int sp = tid >> 7, si = tid & 127;  // staging coords

    for (int cc = 0; cc < 64; ++cc){
        const int qbase = blockIdx.x*256 + cc*4;    // q = t*512 + b
        // stage 4 input rows (one value per thread)
        xts[tid] = fmaf(g_feats[(qbase+sp)*128 + si], siw[si], sib[si]);
        __syncthreads();

        float n[4] = {0.f,0.f,0.f,0.f}, d[4] = {0.f,0.f,0.f,0.f};
        #pragma unroll 4
        for (int ii = 0; ii < 32; ii += 4){
            const int i = i0 + ii;
            float4 x0 = *(const float4*)&xts[i];
            float4 x1 = *(const float4*)&xts[128+i];
            float4 x2 = *(const float4*)&xts[256+i];
            float4 x3 = *(const float4*)&xts[384+i];
            const float xv[4][4] = {{x0.x,x1.x,x2.x,x3.x},{x0.y,x1.y,x2.y,x3.y},
                                    {x0.z,x1.z,x2.z,x3.z},{x0.w,x1.w,x2.w,x3.w}};
            #pragma unroll
            for (int k = 0; k < 4; ++k){
                float2 P = sPQ[((i+k)<<7) + j];
                float h  = sH[((i+k)<<7) + j];
                float ha = fabsf(h);
                #pragma unroll
                for (int r = 0; r < 4; ++r){
                    float tt = fast_tanh(fmaf(xv[k][r], P.x, P.y));
                    n[r] = fmaf(h, tt, n[r]);
                    d[r] = fmaf(ha, tt, d[r]);
                }
            }
        }
        #pragma unroll
        for (int r = 0; r < 4; ++r){
            pn[(qt*4+r)*128 + j] = n[r];
            pd[(qt*4+r)*128 + j] = d[r];
        }
        __syncthreads();
        // quarter qt writes output pair qt
        {
            float sn = pn[(0*4+qt)*128+j] + pn[(1*4+qt)*128+j] + pn[(2*4+qt)*128+j] + pn[(3*4+qt)*128+j];
            float sd = pd[(0*4+qt)*128+j] + pd[(1*4+qt)*128+j] + pd[(2*4+qt)*128+j] + pd[(3*4+qt)*128+j];
            g_wns[(qbase+qt)*128 + j] = sn + hs;
            g_wds[(qbase+qt)*128 + j] = sd + has;
        }
        __syncthreads();
    }
}

// ============================================================
// LTC recurrence: CTA owns 4 batch rows; 512 threads; each thread
// accumulates all 4 rows over a 32-wide i-quarter; quarter q
// combines partials and updates row q.
// ============================================================
__global__ void __launch_bounds__(512) rec_kernel(
    const float* __restrict__ mu,    const float* __restrict__ sigma,
    const float* __restrict__ W,     const float* __restrict__ erev,
    const float* __restrict__ vleak, const float* __restrict__ gleak,
    const float* __restrict__ cmt)
{
    extern __shared__ float sm[];
    float2* rPQ = (float2*)sm;         // [16384]
    float*  rH  = sm + 32768;          // [16384] h2 = 0.5*W*erev
    float*  sV  = rH + 16384;          // [4][128]
    float*  pn  = sV + 512;            // [4 qt][4 row][128]
    float*  pd  = pn + 2048;           // [4 qt][4 row][128]
    float*  hsum  = pd + 2048;         // [128]
    float*  hasum = hsum + 128;        // [128]
    const int tid = threadIdx.x;

    for (int idx = tid; idx < 16384; idx += 512){
        float sg = sigma[idx] * 0.5f;
        rPQ[idx] = make_float2(sg, -mu[idx] * sg);
        rH[idx]  = 0.5f * W[idx] * erev[idx];
    }
    if (tid < 512) { if (tid < 512) sV[tid] = 0.f; }
    __syncthreads();
    if (tid < 128){
        float a = 0.f, bb = 0.f;
        for (int i = 0; i < 128; ++i){ float h = rH[(i<<7)+tid]; a += h; bb += fabsf(h); }
        hsum[tid] = a; hasum[tid] = bb;
    }
    __syncthreads();

    const int j = tid & 127, qt = tid >> 7;
    const int i0 = qt << 5;
    const float cmv = cmt[j];
    const float gl  = gleak[j];
    const float base_n = gl * vleak[j] + hsum[j];
    const float base_d = cmv + gl + hasum[j];
    const int bbase = blockIdx.x * 4;

    for (int t = 0; t < 64; ++t){
        // each thread only needs the sensory terms of its own row (qt)
        const int q = (t*512 + bbase + qt)*128 + j;
        const float c_n = base_n + g_wns[q];
        const float c_d = base_d + g_wds[q];
        for (int u = 0; u < 6; ++u){
            float n[4] = {0.f,0.f,0.f,0.f}, d[4] = {0.f,0.f,0.f,0.f};
            #pragma unroll 4
            for (int ii = 0; ii < 32; ii += 4){
                const int i = i0 + ii;
                float4 v0 = *(const float4*)&sV[i];
                float4 v1 = *(const float4*)&sV[128+i];
                float4 v2 = *(const float4*)&sV[256+i];
                float4 v3 = *(const float4*)&sV[384+i];
                const float vv[4][4] = {{v0.x,v1.x,v2.x,v3.x},{v0.y,v1.y,v2.y,v3.y},
                                        {v0.z,v1.z,v2.z,v3.z},{v0.w,v1.w,v2.w,v3.w}};
                #pragma unroll
                for (int k = 0; k < 4; ++k){
                    float2 P = rPQ[((i+k)<<7) + j];
                    float h  = rH[((i+k)<<7) + j];
                    float ha = fabsf(h);
                    #pragma unroll
                    for (int r = 0; r < 4; ++r){
                        float tt = fast_tanh(fmaf(vv[k][r], P.x, P.y));
                        n[r] = fmaf(h, tt, n[r]);
                        d[r] = fmaf(ha, tt, d[r]);
                    }
                }
            }
            #pragma unroll
            for (int r = 0; r < 4; ++r){
                pn[(qt*4+r)*128 + j] = n[r];
                pd[(qt*4+r)*128 + j] = d[r];
            }
            __syncthreads();
            // quarter qt updates row qt
            {
                float sn = pn[(0*4+qt)*128+j] + pn[(1*4+qt)*128+j] + pn[(2*4+qt)*128+j] + pn[(3*4+qt)*128+j];
                float sd = pd[(0*4+qt)*128+j] + pd[(1*4+qt)*128+j] + pd[(2*4+qt)*128+j] + pd[(3*4+qt)*128+j];
                float vold = sV[qt*128 + j];
                float nv = (fmaf(cmv, vold, c_n) + sn) * fast_rcp(c_d + sd);
                __syncthreads();
                sV[qt*128 + j] = nv;
            }
            __syncthreads();
        }
    }
    g_hT[(bbase + qt)*128 + j] = sV[qt*128 + j];
}

// ============================================================
// head: relu(hT @ fc1^T + b1) @ fc2^T + b2  -> out[512]
// ============================================================
__global__ void __launch_bounds__(64) head_kernel(
    const float* __restrict__ fc1w, const float* __restrict__ fc1b,
    const float* __restrict__ fc2w, const float* __restrict__ fc2b,
    float* __restrict__ out)
{
    __shared__ float sh[128];
    __shared__ float part[2];
    const int b = blockIdx.x, d = threadIdx.x;
    sh[d]      = g_hT[b*128 + d];
    sh[d + 64] = g_hT[b*128 + 64 + d];
    __syncthreads();
    float acc = fc1b[d];
    #pragma unroll 16
    for (int k = 0; k < 128; ++k)
        acc = fmaf(fc1w[d*128 + k], sh[k], acc);
    acc = fmaxf(acc, 0.f) * fc2w[d];
    #pragma unroll
    for (int off = 16; off > 0; off >>= 1)
        acc += __shfl_down_sync(0xffffffffu, acc, off);
    if ((d & 31) == 0) part[d >> 5] = acc;
    __syncthreads();
    if (d == 0) out[b] = part[0] + part[1] + fc2b[0];
}

extern "C" void kernel_launch(void* const* d_in, const int* in_sizes, int n_in,
                              void* d_out, int out_size)
{
    const float* x     = (const float*)d_in[0];
    const float* c1w   = (const float*)d_in[1];
    const float* c1b   = (const float*)d_in[2];
    const float* c2w   = (const float*)d_in[3];
    const float* c2b   = (const float*)d_in[4];
    const float* iw    = (const float*)d_in[5];
    const float* ib    = (const float*)d_in[6];
    const float* smu   = (const float*)d_in[7];
    const float* ssig  = (const float*)d_in[8];
    const float* sW    = (const float*)d_in[9];
    const float* serev = (const float*)d_in[10];
    const float* mu    = (const float*)d_in[11];
    const float* sigma = (const float*)d_in[12];
    const float* W     = (const float*)d_in[13];
    const float* erev  = (const float*)d_in[14];
    const float* vleak = (const float*)d_in[15];
    const float* gleak = (const float*)d_in[16];
    const float* cmt   = (const float*)d_in[17];
    const float* fc1w  = (const float*)d_in[18];
    const float* fc1b  = (const float*)d_in[19];
    const float* fc2w  = (const float*)d_in[20];
    const float* fc2b  = (const float*)d_in[21];
    float* out = (float*)d_out;

    const int SM_C1 = (24*260 + 7680 + 64) * 4;                                   //  55,936 B
    const int SM_C2 = (64*130 + 24576 + 128) * 4;                                 // 132,096 B
    const int SM_SE = (32768 + 16384 + 512 + 2048 + 2048 + 128 + 128 + 128 + 128) * 4; // 217,088 B
    const int SM_RE = (32768 + 16384 + 512 + 2048 + 2048 + 128 + 128) * 4;             // 216,064 B
    cudaFuncSetAttribute(conv1_kernel,   cudaFuncAttributeMaxDynamicSharedMemorySize, SM_C1);
    cudaFuncSetAttribute(conv2_kernel,   cudaFuncAttributeMaxDynamicSharedMemorySize, SM_C2);
    cudaFuncSetAttribute(sensory_kernel, cudaFuncAttributeMaxDynamicSharedMemorySize, SM_SE);
    cudaFuncSetAttribute(rec_kernel,     cudaFuncAttributeMaxDynamicSharedMemorySize, SM_RE);

    conv1_kernel<<<512, 256, SM_C1>>>(x, c1w, c1b);
    conv2_kernel<<<512, 256, SM_C2>>>(c2w, c2b);
    sensory_kernel<<<128, 512, SM_SE>>>(smu, ssig, sW, serev, iw, ib);
    rec_kernel<<<128, 512, SM_RE>>>(mu, sigma, W, erev, vleak, gleak, cmt);
    head_kernel<<<512, 64>>>(fc1w, fc1b, fc2w, fc2b, out);
}

// round 5
// speedup vs baseline: 1.9265x; 1.0671x over previous
#include <cuda_runtime.h>

// ---- scratch (static __device__; no allocations allowed) ----
__device__ float g_h1[512*64*128];      // conv1 output   [b][c=64][t=128]
__device__ float g_feats[64*512*128];   // conv2 output   [t'=64][b][in=128]
__device__ float g_wns[64*512*128];     // sensory num    [t'][b][u]
__device__ float g_wds[64*512*128];     // sensory den    [t'][b][u]
__device__ float g_v[512*128];          // persistent LTC state between chunks

__device__ __forceinline__ float fast_tanh(float x){ float y; asm("tanh.approx.f32 %0, %1;" : "=f"(y) : "f"(x)); return y; }
__device__ __forceinline__ float fast_rcp(float x){ float y; asm("rcp.approx.f32 %0, %1;" : "=f"(y) : "f"(x)); return y; }

// ============================================================
// conv1: x[512,256,24] -> relu -> maxpool2 -> g_h1[512][64][128]
// ============================================================
__global__ void __launch_bounds__(256) conv1_kernel(const float* __restrict__ x,
                                                    const float* __restrict__ w,
                                                    const float* __restrict__ bias)
{
    extern __shared__ float sm[];
    float* xs = sm;               // [24][260], col = t+2 (pad 2 each side)
    float* ws = sm + 24*260;      // [(f*5+k)][64]
    float* bs = ws + 7680;        // [64]
    const int b = blockIdx.x, tid = threadIdx.x;

    for (int idx = tid; idx < 6144; idx += 256){
        int t = idx / 24, f = idx % 24;
        xs[f*260 + t + 2] = x[b*6144 + idx];
    }
    for (int idx = tid; idx < 7680; idx += 256){
        int c = idx / 120, r = idx % 120;   // r = f*5+k
        ws[r*64 + c] = w[idx];
    }
    if (tid < 64) bs[tid] = bias[tid];
    if (tid < 96){  // zero the pad columns 0,1,258,259
        int f = tid >> 2, p = tid & 3;
        int col = (p < 2) ? p : (256 + p);
        xs[f*260 + col] = 0.f;
    }
    __syncthreads();

    const int c = tid & 63, seg = tid >> 6;
    const float bv = bs[c];
    for (int sub = 0; sub < 2; ++sub){
        const int tbase = seg*64 + sub*32;  // pre-pool start
        float acc[32];
        #pragma unroll
        for (int jj = 0; jj < 32; ++jj) acc[jj] = 0.f;
        for (int f = 0; f < 24; ++f){
            float wr[5];
            #pragma unroll
            for (int k = 0; k < 5; ++k) wr[k] = ws[(f*5+k)*64 + c];
            float xr[36];
            #pragma unroll
            for (int ii = 0; ii < 36; ++ii) xr[ii] = xs[f*260 + tbase + ii];
            #pragma unroll
            for (int jj = 0; jj < 32; ++jj){
                float a = acc[jj];
                #pragma unroll
                for (int k = 0; k < 5; ++k) a = fmaf(wr[k], xr[jj+k], a);
                acc[jj] = a;
            }
        }
        const int tp0 = tbase >> 1;
        #pragma unroll
        for (int m = 0; m < 16; ++m){
            float v = fmaxf(fmaxf(acc[2*m], acc[2*m+1]) + bv, 0.f);
            g_h1[(b*64 + c)*128 + tp0 + m] = v;
        }
    }
}

// ============================================================
// conv2: split over output-channel halves; grid = 512 b * 2 halves
// 83KB smem -> 2 CTAs/SM
// ============================================================
__global__ void __launch_bounds__(256) conv2_kernel(const float* __restrict__ w,
                                                    const float* __restrict__ bias)
{
    extern __shared__ float sm[];
    float* xs = sm;                 // [64][130], col = t+1 (pad 1 each side)
    float* ws = xs + 64*130;        // [(cin*3+k)][64]
    float* bs = ws + 12288;         // [64]
    const int b = blockIdx.x >> 1, half = blockIdx.x & 1;
    const int tid = threadIdx.x;

    for (int idx = tid; idx < 8192; idx += 256){
        int cin = idx >> 7, t = idx & 127;
        xs[cin*130 + t + 1] = g_h1[b*8192 + idx];
    }
    for (int idx = tid; idx < 12288; idx += 256){
        int co = idx / 192, r = idx % 192;  // r = cin*3+k
        ws[r*64 + co] = w[(half*64 + co)*192 + r];
    }
    if (tid < 64) bs[tid] = bias[half*64 + tid];
    if (tid < 128){ int cin = tid >> 1, p = tid & 1; xs[cin*130 + (p ? 129 : 0)] = 0.f; }
    __syncthreads();

    const int co = tid & 63, seg = tid >> 6;   // 4 segs x 32 pre-pool t
    const float bv = bs[co];
    const int tbase = seg*32;
    float acc[32];
    #pragma unroll
    for (int jj = 0; jj < 32; ++jj) acc[jj] = 0.f;
    for (int cin = 0; cin < 64; ++cin){
        float wr[3];
        #pragma unroll
        for (int k = 0; k < 3; ++k) wr[k] = ws[(cin*3+k)*64 + co];
        float xr[34];
        #pragma unroll
        for (int ii = 0; ii < 34; ++ii) xr[ii] = xs[cin*130 + tbase + ii];
        #pragma unroll
        for (int jj = 0; jj < 32; ++jj){
            float a = acc[jj];
            #pragma unroll
            for (int k = 0; k < 3; ++k) a = fmaf(wr[k], xr[jj+k], a);
            acc[jj] = a;
        }
    }
    const int co_g = half*64 + co;
    const int tp0 = seg*16;
    #pragma unroll
    for (int m = 0; m < 16; ++m){
        float v = fmaxf(fmaxf(acc[2*m], acc[2*m+1]) + bv, 0.f);
        g_feats[((tp0 + m)*512 + b)*128 + co_g] = v;
    }
}

// ============================================================
// sensory (chunked): quads g in [0,nquads), pair base = tbeg*512 + g*4
// 512 threads: 4 i-quarters x 128 j; 4 pairs per quad.
// ============================================================
__global__ void __launch_bounds__(512) sensory_kernel(
    int tbeg, int nquads,
    const float* __restrict__ smu, const float* __restrict__ ssig,
    const float* __restrict__ sW,  const float* __restrict__ serev,
    const float* __restrict__ iw,  const float* __restrict__ ib)
{
    extern __shared__ float sm[];
    float2* sPQ = (float2*)sm;         // [16384]
    float*  sH  = sm + 32768;          // [16384] h2 = 0.5*W*erev
    float*  xts = sH + 16384;          // [4][128]
    float*  pn  = xts + 512;           // [4 qt][4 pair][128]
    float*  pd  = pn + 2048;           // [4 qt][4 pair][128]
    float*  hsum  = pd + 2048;         // [128]
    float*  hasum = hsum + 128;        // [128]
    float*  siw   = hasum + 128;       // [128]
    float*  sib   = siw + 128;         // [128]
    const int tid = threadIdx.x;

    for (int idx = tid; idx < 16384; idx += 512){
        float sg = ssig[idx] * 0.5f;
        sPQ[idx] = make_float2(sg, -smu[idx] * sg);
        sH[idx]  = 0.5f * sW[idx] * serev[idx];
    }
    if (tid < 128){ siw[tid] = iw[tid]; sib[tid] = ib[tid]; }
    __syncthreads();
    if (tid < 128){
        float a = 0.f, bb = 0.f;
        for (int i = 0; i < 128; ++i){ float h = sH[(i<<7)+tid]; a += h; bb += fabsf(h); }
        hsum[tid] = a; hasum[tid] = bb;
    }
    __syncthreads();

    const int j = tid & 127, qt = tid >> 7;   // quarter 0..3
    const int i0 = qt << 5;
    const float hs = hsum[j], has = hasum[j];
    const int sp = tid >> 7, si = tid & 127;  // staging coords
    const int pair0 = tbeg * 512;

    for (int g = blockIdx.x; g < nquads; g += gridDim.x){
        const int qbase = pair0 + g*4;
        xts[tid] = fmaf(g_feats[(qbase+sp)*128 + si], siw[si], sib[si]);
        __syncthreads();

        float n[4] = {0.f,0.f,0.f,0.f}, d[4] = {0.f,0.f,0.f,0.f};
        #pragma unroll 4
        for (int ii = 0; ii < 32; ii += 4){
            const int i = i0 + ii;
            float4 x0 = *(const float4*)&xts[i];
            float4 x1 = *(const float4*)&xts[128+i];
            float4 x2 = *(const float4*)&xts[256+i];
            float4 x3 = *(const float4*)&xts[384+i];
            const float xv[4][4] = {{x0.x,x1.x,x2.x,x3.x},{x0.y,x1.y,x2.y,x3.y},
                                    {x0.z,x1.z,x2.z,x3.z},{x0.w,x1.w,x2.w,x3.w}};
            #pragma unroll
            for (int k = 0; k < 4; ++k){
                float2 P = sPQ[((i+k)<<7) + j];
                float h  = sH[((i+k)<<7) + j];
                float ha = fabsf(h);
                #pragma unroll
                for (int r = 0; r < 4; ++r){
                    float tt = fast_tanh(fmaf(xv[k][r], P.x, P.y));
                    n[r] = fmaf(h, tt, n[r]);
                    d[r] = fmaf(ha, tt, d[r]);
                }
            }
        }
        #pragma unroll
        for (int r = 0; r < 4; ++r){
            pn[(qt*4+r)*128 + j] = n[r];
            pd[(qt*4+r)*128 + j] = d[r];
        }
        __syncthreads();
        {
            float sn = pn[(0*4+qt)*128+j] + pn[(1*4+qt)*128+j] + pn[(2*4+qt)*128+j] + pn[(3*4+qt)*128+j];
            float sd = pd[(0*4+qt)*128+j] + pd[(1*4+qt)*128+j] + pd[(2*4+qt)*128+j] + pd[(3*4+qt)*128+j];
            g_wns[(qbase+qt)*128 + j] = sn + hs;
            g_wds[(qbase+qt)*128 + j] = sd + has;
        }
        __syncthreads();
    }
}

// ============================================================
// LTC recurrence chunk [tbeg, tend): CTA owns 4 batch rows.
// State persisted in g_v between chunk kernels.
// ============================================================
__global__ void __launch_bounds__(512) rec_kernel(
    int tbeg, int tend, int zeroInit,
    const float* __restrict__ mu,    const float* __restrict__ sigma,
    const float* __restrict__ W,     const float* __restrict__ erev,
    const float* __restrict__ vleak, const float* __restrict__ gleak,
    const float* __restrict__ cmt)
{
    extern __shared__ float sm[];
    float2* rPQ = (float2*)sm;         // [16384]
    float*  rH  = sm + 32768;          // [16384] h2 = 0.5*W*erev
    float*  sV  = rH + 16384;          // [4][128]
    float*  pn  = sV + 512;            // [4 qt][4 row][128]
    float*  pd  = pn + 2048;           // [4 qt][4 row][128]
    float*  hsum  = pd + 2048;         // [128]
    float*  hasum = hsum + 128;        // [128]
    const int tid = threadIdx.x;
    const int bbase = blockIdx.x * 4;

    for (int idx = tid; idx < 16384; idx += 512){
        float sg = sigma[idx] * 0.5f;
        rPQ[idx] = make_float2(sg, -mu[idx] * sg);
        rH[idx]  = 0.5f * W[idx] * erev[idx];
    }
    sV[tid] = zeroInit ? 0.f : g_v[(bbase + (tid>>7))*128 + (tid & 127)];
    __syncthreads();
    if (tid < 128){
        float a = 0.f, bb = 0.f;
        for (int i = 0; i < 128; ++i){ float h = rH[(i<<7)+tid]; a += h; bb += fabsf(h); }
        hsum[tid] = a; hasum[tid] = bb;
    }
    __syncthreads();

    const int j = tid & 127, qt = tid >> 7;
    const int i0 = qt << 5;
    const float cmv = cmt[j];
    const float gl  = gleak[j];
    const float base_n = gl * vleak[j] + hsum[j];
    const float base_d = cmv + gl + hasum[j];

    for (int t = tbeg; t < tend; ++t){
        const int q = (t*512 + bbase + qt)*128 + j;
        const float c_n = base_n + g_wns[q];
        const float c_d = base_d + g_wds[q];
        for (int u = 0; u < 6; ++u){
            float n[4] = {0.f,0.f,0.f,0.f}, d[4] = {0.f,0.f,0.f,0.f};
            #pragma unroll 4
            for (int ii = 0; ii < 32; ii += 4){
                const int i = i0 + ii;
                float4 v0 = *(const float4*)&sV[i];
                float4 v1 = *(const float4*)&sV[128+i];
                float4 v2 = *(const float4*)&sV[256+i];
                float4 v3 = *(const float4*)&sV[384+i];
                const float vv[4][4] = {{v0.x,v1.x,v2.x,v3.x},{v0.y,v1.y,v2.y,v3.y},
                                        {v0.z,v1.z,v2.z,v3.z},{v0.w,v1.w,v2.w,v3.w}};
                #pragma unroll
                for (int k = 0; k < 4; ++k){
                    float2 P = rPQ[((i+k)<<7) + j];
                    float h  = rH[((i+k)<<7) + j];
                    float ha = fabsf(h);
                    #pragma unroll
                    for (int r = 0; r < 4; ++r){
                        float tt = fast_tanh(fmaf(vv[k][r], P.x, P.y));
                        n[r] = fmaf(h, tt, n[r]);
                        d[r] = fmaf(ha, tt, d[r]);
                    }
                }
            }
            #pragma unroll
            for (int r = 0; r < 4; ++r){
                pn[(qt*4+r)*128 + j] = n[r];
                pd[(qt*4+r)*128 + j] = d[r];
            }
            __syncthreads();
            {
                float sn = pn[(0*4+qt)*128+j] + pn[(1*4+qt)*128+j] + pn[(2*4+qt)*128+j] + pn[(3*4+qt)*128+j];
                float sd = pd[(0*4+qt)*128+j] + pd[(1*4+qt)*128+j] + pd[(2*4+qt)*128+j] + pd[(3*4+qt)*128+j];
                float vold = sV[qt*128 + j];
                float nv = (fmaf(cmv, vold, c_n) + sn) * fast_rcp(c_d + sd);
                __syncthreads();
                sV[qt*128 + j] = nv;
            }
            __syncthreads();
        }
    }
    g_v[(bbase + qt)*128 + j] = sV[qt*128 + j];
}

// ============================================================
// head: relu(v @ fc1^T + b1) @ fc2^T + b2  -> out[512]
// ============================================================
__global__ void __launch_bounds__(64) head_kernel(
    const float* __restrict__ fc1w, const float* __restrict__ fc1b,
    const float* __restrict__ fc2w, const float* __restrict__ fc2b,
    float* __restrict__ out)
{
    __shared__ float sh[128];
    __shared__ float part[2];
    const int b = blockIdx.x, d = threadIdx.x;
    sh[d]      = g_v[b*128 + d];
    sh[d + 64] = g_v[b*128 + 64 + d];
    __syncthreads();
    float acc = fc1b[d];
    #pragma unroll 16
    for (int k = 0; k < 128; ++k)
        acc = fmaf(fc1w[d*128 + k], sh[k], acc);
    acc = fmaxf(acc, 0.f) * fc2w[d];
    #pragma unroll
    for (int off = 16; off > 0; off >>= 1)
        acc += __shfl_down_sync(0xffffffffu, acc, off);
    if ((d & 31) == 0) part[d >> 5] = acc;
    __syncthreads();
    if (d == 0) out[b] = part[0] + part[1] + fc2b[0];
}

extern "C" void kernel_launch(void* const* d_in, const int* in_sizes, int n_in,
                              void* d_out, int out_size)
{
    const float* x     = (const float*)d_in[0];
    const float* c1w   = (const float*)d_in[1];
    const float* c1b   = (const float*)d_in[2];
    const float* c2w   = (const float*)d_in[3];
    const float* c2b   = (const float*)d_in[4];
    const float* iw    = (const float*)d_in[5];
    const float* ib    = (const float*)d_in[6];
    const float* smu   = (const float*)d_in[7];
    const float* ssig  = (const float*)d_in[8];
    const float* sW    = (const float*)d_in[9];
    const float* serev = (const float*)d_in[10];
    const float* mu    = (const float*)d_in[11];
    const float* sigma = (const float*)d_in[12];
    const float* W     = (const float*)d_in[13];
    const float* erev  = (const float*)d_in[14];
    const float* vleak = (const float*)d_in[15];
    const float* gleak = (const float*)d_in[16];
    const float* cmt   = (const float*)d_in[17];
    const float* fc1w  = (const float*)d_in[18];
    const float* fc1b  = (const float*)d_in[19];
    const float* fc2w  = (const float*)d_in[20];
    const float* fc2b  = (const float*)d_in[21];
    float* out = (float*)d_out;

    const int SM_C1 = (24*260 + 7680 + 64) * 4;                                        //  55,936 B
    const int SM_C2 = (64*130 + 12288 + 64) * 4;                                       //  82,688 B
    const int SM_SE = (32768 + 16384 + 512 + 2048 + 2048 + 128 + 128 + 128 + 128) * 4; // 217,088 B
    const int SM_RE = (32768 + 16384 + 512 + 2048 + 2048 + 128 + 128) * 4;             // 216,064 B

    static bool inited = false;
    static cudaStream_t s2;
    static cudaEvent_t evFork, evChunk[5];
    if (!inited){
        cudaStreamCreate(&s2);
        cudaEventCreateWithFlags(&evFork, cudaEventDisableTiming);
        for (int k = 0; k < 5; ++k)
            cudaEventCreateWithFlags(&evChunk[k], cudaEventDisableTiming);
        cudaFuncSetAttribute(conv1_kernel,   cudaFuncAttributeMaxDynamicSharedMemorySize, SM_C1);
        cudaFuncSetAttribute(conv2_kernel,   cudaFuncAttributeMaxDynamicSharedMemorySize, SM_C2);
        cudaFuncSetAttribute(sensory_kernel, cudaFuncAttributeMaxDynamicSharedMemorySize, SM_SE);
        cudaFuncSetAttribute(rec_kernel,     cudaFuncAttributeMaxDynamicSharedMemorySize, SM_RE);
        inited = true;
    }

    conv1_kernel<<<512, 256, SM_C1>>>(x, c1w, c1b);
    conv2_kernel<<<1024, 256, SM_C2>>>(c2w, c2b);

    // sensory runway: t in [0, 24) on the full chip
    sensory_kernel<<<128, 512, SM_SE>>>(0, 24*128, smu, ssig, sW, serev, iw, ib);

    // fork: remaining sensory chunks (8 t each) on 20 CTAs, concurrent with rec
    cudaEventRecord(evFork, 0);
    cudaStreamWaitEvent(s2, evFork, 0);
    for (int k = 0; k < 5; ++k){
        sensory_kernel<<<20, 512, SM_SE, s2>>>(24 + 8*k, 8*128, smu, ssig, sW, serev, iw, ib);
        cudaEventRecord(evChunk[k], s2);
    }

    // rec chunks on the main stream
    rec_kernel<<<128, 512, SM_RE>>>(0, 24, 1, mu, sigma, W, erev, vleak, gleak, cmt);
    for (int k = 0; k < 5; ++k){
        cudaStreamWaitEvent(0, evChunk[k], 0);
        rec_kernel<<<128, 512, SM_RE>>>(24 + 8*k, 32 + 8*k, 0, mu, sigma, W, erev, vleak, gleak, cmt);
    }

    head_kernel<<<512, 64>>>(fc1w, fc1b, fc2w, fc2b, out);
}

// round 7
// speedup vs baseline: 1.9463x; 1.0103x over previous
#include <cuda_runtime.h>

// ---- scratch (static __device__; no allocations allowed) ----
__device__ float g_h1[512*64*128];      // conv1 output   [b][c=64][t=128]
__device__ float g_feats[64*512*128];   // conv2 output   [t'=64][b][in=128]
__device__ float g_wns[64*512*128];     // sensory num    [t'][b][u]
__device__ float g_wds[64*512*128];     // sensory den    [t'][b][u]
__device__ float g_v[512*128];          // persistent LTC state between chunks
__device__ float2 g_sPQ[16384];         // sensory (p,q) folded params
__device__ float  g_sH[16384];          // sensory h2 = 0.5*W*erev
__device__ float2 g_rPQ[16384];         // rec (p,q)
__device__ float  g_rH[16384];          // rec h2
__device__ float  g_hs[512];            // [sens hsum | sens hasum | rec hsum | rec hasum]

__device__ __forceinline__ float fast_tanh(float x){ float y; asm("tanh.approx.f32 %0, %1;" : "=f"(y) : "f"(x)); return y; }
__device__ __forceinline__ float fast_rcp(float x){ float y; asm("rcp.approx.f32 %0, %1;" : "=f"(y) : "f"(x)); return y; }

// ============================================================
// prep: fold params (runs concurrent with conv1 on s2)
// ============================================================
__global__ void __launch_bounds__(256) prep_kernel(
    const float* __restrict__ smu, const float* __restrict__ ssig,
    const float* __restrict__ sW,  const float* __restrict__ serev,
    const float* __restrict__ mu,  const float* __restrict__ sigma,
    const float* __restrict__ W,   const float* __restrict__ erev)
{
    const int stride = gridDim.x * blockDim.x;
    for (int idx = blockIdx.x*blockDim.x + threadIdx.x; idx < 16384; idx += stride){
        float sg = ssig[idx] * 0.5f;
        g_sPQ[idx] = make_float2(sg, -smu[idx] * sg);
        g_sH[idx]  = 0.5f * sW[idx] * serev[idx];
        float rg = sigma[idx] * 0.5f;
        g_rPQ[idx] = make_float2(rg, -mu[idx] * rg);
        g_rH[idx]  = 0.5f * W[idx] * erev[idx];
    }
}

__global__ void __launch_bounds__(128) hsums_kernel()
{
    const int j = threadIdx.x;
    const float* src = blockIdx.x ? g_rH : g_sH;
    const int base = blockIdx.x ? 256 : 0;
    float a = 0.f, bb = 0.f;
    for (int i = 0; i < 128; ++i){ float h = src[(i<<7)+j]; a += h; bb += fabsf(h); }
    g_hs[base + j] = a;
    g_hs[base + 128 + j] = bb;
}

// ============================================================
// conv1: grid 1024 = b x t-half; 44KB smem -> 5 CTAs/SM
// ============================================================
__global__ void __launch_bounds__(256) conv1_kernel(const float* __restrict__ x,
                                                    const float* __restrict__ w,
                                                    const float* __restrict__ bias)
{
    extern __shared__ float sm[];
    float* xs = sm;               // [24][136], col = t_g - half*128 + 2
    float* ws = sm + 24*136;      // [(f*5+k)][64]
    float* bs = ws + 7680;        // [64]
    const int b = blockIdx.x >> 1, half = blockIdx.x & 1;
    const int tid = threadIdx.x;
    const int t0 = half * 128;

    for (int idx = tid; idx < 24*132; idx += 256){
        int tl = idx / 24, f = idx % 24;
        int tg = t0 - 2 + tl;
        xs[f*136 + tl] = (tg >= 0 && tg < 256) ? x[b*6144 + tg*24 + f] : 0.f;
    }
    for (int idx = tid; idx < 7680; idx += 256){
        int c = idx / 120, r = idx % 120;   // r = f*5+k
        ws[r*64 + c] = w[idx];
    }
    if (tid < 64) bs[tid] = bias[tid];
    __syncthreads();

    const int c = tid & 63, seg = tid >> 6;   // 4 segs x 32 pre-pool t
    const float bv = bs[c];
    float acc[32];
    #pragma unroll
    for (int jj = 0; jj < 32; ++jj) acc[jj] = 0.f;
    for (int f = 0; f < 24; ++f){
        float wr[5];
        #pragma unroll
        for (int k = 0; k < 5; ++k) wr[k] = ws[(f*5+k)*64 + c];
        float xr[36];
        #pragma unroll
        for (int ii = 0; ii < 36; ++ii) xr[ii] = xs[f*136 + seg*32 + ii];
        #pragma unroll
        for (int jj = 0; jj < 32; ++jj){
            float a = acc[jj];
            #pragma unroll
            for (int k = 0; k < 5; ++k) a = fmaf(wr[k], xr[jj+k], a);
            acc[jj] = a;
        }
    }
    const int tp0 = half*64 + seg*16;
    #pragma unroll
    for (int m = 0; m < 16; ++m){
        float v = fmaxf(fmaxf(acc[2*m], acc[2*m+1]) + bv, 0.f);
        g_h1[(b*64 + c)*128 + tp0 + m] = v;
    }
}

// ============================================================
// conv2: split over output-channel halves; grid = 512 b * 2 halves
// ============================================================
__global__ void __launch_bounds__(256) conv2_kernel(const float* __restrict__ w,
                                                    const float* __restrict__ bias)
{
    extern __shared__ float sm[];
    float* xs = sm;                 // [64][130], col = t+1 (pad 1 each side)
    float* ws = xs + 64*130;        // [(cin*3+k)][64]
    float* bs = ws + 12288;         // [64]
    const int b = blockIdx.x >> 1, half = blockIdx.x & 1;
    const int tid = threadIdx.x;

    for (int idx = tid; idx < 8192; idx += 256){
        int cin = idx >> 7, t = idx & 127;
        xs[cin*130 + t + 1] = g_h1[b*8192 + idx];
    }
    for (int idx = tid; idx < 12288; idx += 256){
        int co = idx / 192, r = idx % 192;  // r = cin*3+k
        ws[r*64 + co] = w[(half*64 + co)*192 + r];
    }
    if (tid < 64) bs[tid] = bias[half*64 + tid];
    if (tid < 128){ int cin = tid >> 1, p = tid & 1; xs[cin*130 + (p ? 129 : 0)] = 0.f; }
    __syncthreads();

    const int co = tid & 63, seg = tid >> 6;   // 4 segs x 32 pre-pool t
    const float bv = bs[co];
    const int tbase = seg*32;
    float acc[32];
    #pragma unroll
    for (int jj = 0; jj < 32; ++jj) acc[jj] = 0.f;
    for (int cin = 0; cin < 64; ++cin){
        float wr[3];
        #pragma unroll
        for (int k = 0; k < 3; ++k) wr[k] = ws[(cin*3+k)*64 + co];
        float xr[34];
        #pragma unroll
        for (int ii = 0; ii < 34; ++ii) xr[ii] = xs[cin*130 + tbase + ii];
        #pragma unroll
        for (int jj = 0; jj < 32; ++jj){
            float a = acc[jj];
            #pragma unroll
            for (int k = 0; k < 3; ++k) a = fmaf(wr[k], xr[jj+k], a);
            acc[jj] = a;
        }
    }
    const int co_g = half*64 + co;
    const int tp0 = seg*16;
    #pragma unroll
    for (int m = 0; m < 16; ++m){
        float v = fmaxf(fmaxf(acc[2*m], acc[2*m+1]) + bv, 0.f);
        g_feats[((tp0 + m)*512 + b)*128 + co_g] = v;
    }
}

// ============================================================
// sensory (chunked): quads g in [0,nquads), pair base = tbeg*512 + g*4
// ============================================================
__global__ void __launch_bounds__(512) sensory_kernel(
    int tbeg, int nquads,
    const float* __restrict__ iw, const float* __restrict__ ib)
{
    extern __shared__ float sm[];
    float2* sPQ = (float2*)sm;         // [16384]
    float*  sH  = sm + 32768;          // [16384]
    float*  xts = sH + 16384;          // [4][128]
    float*  pn  = xts + 512;           // [4 qt][4 pair][128]
    float*  pd  = pn + 2048;           // [4 qt][4 pair][128]
    float*  siw = pd + 2048;           // [128]
    float*  sib = siw + 128;           // [128]
    const int tid = threadIdx.x;

    for (int idx = tid; idx < 16384; idx += 512){
        sPQ[idx] = g_sPQ[idx];
        sH[idx]  = g_sH[idx];
    }
    if (tid < 128){ siw[tid] = iw[tid]; sib[tid] = ib[tid]; }
    __syncthreads();

    const int j = tid & 127, qt = tid >> 7;
    const int i0 = qt << 5;
    const float hs = g_hs[j], has = g_hs[128 + j];
    const int sp = tid >> 7, si = tid & 127;
    const int pair0 = tbeg * 512;

    for (int g = blockIdx.x; g < nquads; g += gridDim.x){
        const int qbase = pair0 + g*4;
        xts[tid] = fmaf(g_feats[(qbase+sp)*128 + si], siw[si], sib[si]);
        __syncthreads();

        float n[4] = {0.f,0.f,0.f,0.f}, d[4] = {0.f,0.f,0.f,0.f};
        #pragma unroll 4
        for (int ii = 0; ii < 32; ii += 4){
            const int i = i0 + ii;
            float4 x0 = *(const float4*)&xts[i];
            float4 x1 = *(const float4*)&xts[128+i];
            float4 x2 = *(const float4*)&xts[256+i];
            float4 x3 = *(const float4*)&xts[384+i];
            const float xv[4][4] = {{x0.x,x1.x,x2.x,x3.x},{x0.y,x1.y,x2.y,x3.y},
                                    {x0.z,x1.z,x2.z,x3.z},{x0.w,x1.w,x2.w,x3.w}};
            #pragma unroll
            for (int k = 0; k < 4; ++k){
                float2 P = sPQ[((i+k)<<7) + j];
                float h  = sH[((i+k)<<7) + j];
                float ha = fabsf(h);
                #pragma unroll
                for (int r = 0; r < 4; ++r){
                    float tt = fast_tanh(fmaf(xv[k][r], P.x, P.y));
                    n[r] = fmaf(h, tt, n[r]);
                    d[r] = fmaf(ha, tt, d[r]);
                }
            }
        }
        #pragma unroll
        for (int r = 0; r < 4; ++r){
            pn[(qt*4+r)*128 + j] = n[r];
            pd[(qt*4+r)*128 + j] = d[r];
        }
        __syncthreads();
        {
            float sn = pn[(0*4+qt)*128+j] + pn[(1*4+qt)*128+j] + pn[(2*4+qt)*128+j] + pn[(3*4+qt)*128+j];
            float sd = pd[(0*4+qt)*128+j] + pd[(1*4+qt)*128+j] + pd[(2*4+qt)*128+j] + pd[(3*4+qt)*128+j];
            g_wns[(qbase+qt)*128 + j] = sn + hs;
            g_wds[(qbase+qt)*128 + j] = sd + has;
        }
        __syncthreads();
    }
}

// ============================================================
// LTC recurrence chunk [tbeg, tend); fused MLP head when tend==64
// ============================================================
__global__ void __launch_bounds__(512) rec_kernel(
    int tbeg, int tend, int zeroInit,
    const float* __restrict__ vleak, const float* __restrict__ gleak,
    const float* __restrict__ cmt,
    const float* __restrict__ fc1w, const float* __restrict__ fc1b,
    const float* __restrict__ fc2w, const float* __restrict__ fc2b,
    float* __restrict__ out)
{
    extern __shared__ float sm[];
    float2* rPQ = (float2*)sm;         // [16384]
    float*  rH  = sm + 32768;          // [16384]
    float*  sV  = rH + 16384;          // [4][128]
    float*  pn  = sV + 512;            // [4 qt][4 row][128]
    float*  pd  = pn + 2048;           // [4 qt][4 row][128]
    const int tid = threadIdx.x;
    const int bbase = blockIdx.x * 4;

    for (int idx = tid; idx < 16384; idx += 512){
        rPQ[idx] = g_rPQ[idx];
        rH[idx]  = g_rH[idx];
    }
    sV[tid] = zeroInit ? 0.f : g_v[(bbase + (tid>>7))*128 + (tid & 127)];
    __syncthreads();

    const int j = tid & 127, qt = tid >> 7;
    const int i0 = qt << 5;
    const float cmv = cmt[j];
    const float gl  = gleak[j];
    const float base_n = gl * vleak[j] + g_hs[256 + j];
    const float base_d = cmv + gl + g_hs[384 + j];

    for (int t = tbeg; t < tend; ++t){
        const int q = (t*512 + bbase + qt)*128 + j;
        const float c_n = base_n + g_wns[q];
        const float c_d = base_d + g_wds[q];
        for (int u = 0; u < 6; ++u){
            float n[4] = {0.f,0.f,0.f,0.f}, d[4] = {0.f,0.f,0.f,0.f};
            #pragma unroll 4
            for (int ii = 0; ii < 32; ii += 4){
                const int i = i0 + ii;
                float4 v0 = *(const float4*)&sV[i];
                float4 v1 = *(const float4*)&sV[128+i];
                float4 v2 = *(const float4*)&sV[256+i];
                float4 v3 = *(const float4*)&sV[384+i];
                const float vv[4][4] = {{v0.x,v1.x,v2.x,v3.x},{v0.y,v1.y,v2.y,v3.y},
                                        {v0.z,v1.z,v2.z,v3.z},{v0.w,v1.w,v2.w,v3.w}};
                #pragma unroll
                for (int k = 0; k < 4; ++k){
                    float2 P = rPQ[((i+k)<<7) + j];
                    float h  = rH[((i+k)<<7) + j];
                    float ha = fabsf(h);
                    #pragma unroll
                    for (int r = 0; r < 4; ++r){
                        float tt = fast_tanh(fmaf(vv[k][r], P.x, P.y));
                        n[r] = fmaf(h, tt, n[r]);
                        d[r] = fmaf(ha, tt, d[r]);
                    }
                }
            }
            #pragma unroll
            for (int r = 0; r < 4; ++r){
                pn[(qt*4+r)*128 + j] = n[r];
                pd[(qt*4+r)*128 + j] = d[r];
            }
            __syncthreads();
            {
                float sn = pn[(0*4+qt)*128+j] + pn[(1*4+qt)*128+j] + pn[(2*4+qt)*128+j] + pn[(3*4+qt)*128+j];
                float sd = pd[(0*4+qt)*128+j] + pd[(1*4+qt)*128+j] + pd[(2*4+qt)*128+j] + pd[(3*4+qt)*128+j];
                float vold = sV[qt*128 + j];
                float nv = (fmaf(cmv, vold, c_n) + sn) * fast_rcp(c_d + sd);
                __syncthreads();
                sV[qt*128 + j] = nv;
            }
            __syncthreads();
        }
    }

    if (tend < 64){
        g_v[(bbase + qt)*128 + j] = sV[qt*128 + j];
    } else {
        // fused head: 64 threads per row compute relu(fc1.v+b1)*fc2, reduce
        const int d2 = tid & 127;
        if (d2 < 64){
            float acc = fc1b[d2];
            const float* vrow = sV + qt*128;
            #pragma unroll 16
            for (int k = 0; k < 128; ++k)
                acc = fmaf(fc1w[d2*128 + k], vrow[k], acc);
            acc = fmaxf(acc, 0.f) * fc2w[d2];
            #pragma unroll
            for (int off = 16; off > 0; off >>= 1)
                acc += __shfl_down_sync(0xffffffffu, acc, off);
            if ((d2 & 31) == 0) pn[qt*2 + (d2 >> 5)] = acc;
        }
        __syncthreads();
        if (d2 == 0) out[bbase + qt] = pn[qt*2] + pn[qt*2 + 1] + fc2b[0];
    }
}

extern "C" void kernel_launch(void* const* d_in, const int* in_sizes, int n_in,
                              void* d_out, int out_size)
{
    const float* x     = (const float*)d_in[0];
    const float* c1w   = (const float*)d_in[1];
    const float* c1b   = (const float*)d_in[2];
    const float* c2w   = (const float*)d_in[3];
    const float* c2b   = (const float*)d_in[4];
    const float* iw    = (const float*)d_in[5];
    const float* ib    = (const float*)d_in[6];
    const float* smu   = (const float*)d_in[7];
    const float* ssig  = (const float*)d_in[8];
    const float* sW    = (const float*)d_in[9];
    const float* serev = (const float*)d_in[10];
    const float* mu    = (const float*)d_in[11];
    const float* sigma = (const float*)d_in[12];
    const float* W     = (const float*)d_in[13];
    const float* erev  = (const float*)d_in[14];
    const float* vleak = (const float*)d_in[15];
    const float* gleak = (const float*)d_in[16];
    const float* cmt   = (const float*)d_in[17];
    const float* fc1w  = (const float*)d_in[18];
    const float* fc1b  = (const float*)d_in[19];
    const float* fc2w  = (const float*)d_in[20];
    const float* fc2b  = (const float*)d_in[21];
    float* out = (float*)d_out;

    const int SM_C1 = (24*136 + 7680 + 64) * 4;                         //  44,032 B
    const int SM_C2 = (64*130 + 12288 + 64) * 4;                        //  82,688 B
    const int SM_SE = (32768 + 16384 + 512 + 2048 + 2048 + 256) * 4;    // 216,064 B
    const int SM_RE = (32768 + 16384 + 512 + 2048 + 2048) * 4;          // 215,040 B

    static bool inited = false;
    static cudaStream_t s2;
    static cudaEvent_t evStart, evPrep, evFork, evChunk[5];
    if (!inited){
        cudaStreamCreate(&s2);
        cudaEventCreateWithFlags(&evStart, cudaEventDisableTiming);
        cudaEventCreateWithFlags(&evPrep,  cudaEventDisableTiming);
        cudaEventCreateWithFlags(&evFork,  cudaEventDisableTiming);
        for (int k = 0; k < 5; ++k)
            cudaEventCreateWithFlags(&evChunk[k], cudaEventDisableTiming);
        cudaFuncSetAttribute(conv1_kernel,   cudaFuncAttributeMaxDynamicSharedMemorySize, SM_C1);
        cudaFuncSetAttribute(conv2_kernel,   cudaFuncAttributeMaxDynamicSharedMemorySize, SM_C2);
        cudaFuncSetAttribute(sensory_kernel, cudaFuncAttributeMaxDynamicSharedMemorySize, SM_SE);
        cudaFuncSetAttribute(rec_kernel,     cudaFuncAttributeMaxDynamicSharedMemorySize, SM_RE);
        inited = true;
    }

    // fork s2 from the capture-origin stream BEFORE launching on it
    cudaEventRecord(evStart, 0);
    cudaStreamWaitEvent(s2, evStart, 0);

    // param prep on s2, concurrent with convs
    prep_kernel<<<128, 256, 0, s2>>>(smu, ssig, sW, serev, mu, sigma, W, erev);
    hsums_kernel<<<2, 128, 0, s2>>>();
    cudaEventRecord(evPrep, s2);

    conv1_kernel<<<1024, 256, SM_C1>>>(x, c1w, c1b);
    conv2_kernel<<<1024, 256, SM_C2>>>(c2w, c2b);

    // sensory runway: t in [0, 24) on the full chip
    cudaStreamWaitEvent(0, evPrep, 0);
    sensory_kernel<<<148, 512, SM_SE>>>(0, 24*128, iw, ib);

    // fork: remaining sensory chunks (8 t each) on 20 CTAs, concurrent with rec
    cudaEventRecord(evFork, 0);
    cudaStreamWaitEvent(s2, evFork, 0);
    for (int k = 0; k < 5; ++k){
        sensory_kernel<<<20, 512, SM_SE, s2>>>(24 + 8*k, 8*128, iw, ib);
        cudaEventRecord(evChunk[k], s2);
    }

    // rec chunks on the main stream
    rec_kernel<<<128, 512, SM_RE>>>(0, 24, 1, vleak, gleak, cmt, fc1w, fc1b, fc2w, fc2b, out);
    for (int k = 0; k < 5; ++k){
        cudaStreamWaitEvent(0, evChunk[k], 0);
        rec_kernel<<<128, 512, SM_RE>>>(24 + 8*k, 32 + 8*k, 0, vleak, gleak, cmt, fc1w, fc1b, fc2w, fc2b, out);
    }
}